// round 3
// baseline (speedup 1.0000x reference)
#include <cuda_runtime.h>
#include <math.h>

#define T_   2048
#define B_   8
#define D_   1024
#define HD   64      // d
#define NM_  8
#define MP1  9
#define NT   (T_*B_)     // 16384 tokens
#define NKV  576         // Mp1 * d

// ---------------- static device scratch (no runtime alloc allowed) ----------------
__device__ float g_Q[NT*HD];                       // 4 MB
__device__ float g_K[(size_t)NT*NKV];              // 37.75 MB
__device__ float g_V[(size_t)NT*NKV];              // 37.75 MB
#define NSLOT (B_*MP1*32)                          // 2304 chunk slots
__device__ float g_G[(size_t)NSLOT*HD*HD];         // per-chunk K^T V
__device__ float g_S[(size_t)NSLOT*HD*HD];         // per-chunk starting state
__device__ int   g_tok[B_*NM_*T_];                 // packed token time per (b,m)
__device__ float g_pa [B_*NM_*T_];                 // packed alpha per (b,m)
__device__ int   g_cnt[B_*NM_];                    // segment lengths
__device__ unsigned char g_m1[NT], g_m2[NT];
__device__ float g_a1[NT], g_a2[NT];

// ---------------- zero output ----------------
__global__ void zero_kernel(float* __restrict__ out, int n)
{
    int i = blockIdx.x * blockDim.x + threadIdx.x;
    if (i < n) out[i] = 0.f;
}

// ---------------- gating: logits -> top2 + normalized weights ----------------
// one warp per token; softmax is monotonic so top-k on logits; normalized
// softmax weights reduce to a1 = 1/(1+exp(l2-l1)).
__global__ void gate_kernel(const float* __restrict__ X,
                            const float* __restrict__ Wg,
                            const float* __restrict__ bg)
{
    int warp = (blockIdx.x * blockDim.x + threadIdx.x) >> 5;
    int lane = threadIdx.x & 31;
    if (warp >= NT) return;
    const float* x = X + (size_t)warp * D_;
    float s[8];
    #pragma unroll
    for (int j = 0; j < 8; j++) s[j] = 0.f;
    for (int i = lane; i < D_; i += 32) {
        float xv = x[i];
        float4 w0 = *reinterpret_cast<const float4*>(Wg + (size_t)i*8);
        float4 w1 = *reinterpret_cast<const float4*>(Wg + (size_t)i*8 + 4);
        s[0] = fmaf(xv, w0.x, s[0]); s[1] = fmaf(xv, w0.y, s[1]);
        s[2] = fmaf(xv, w0.z, s[2]); s[3] = fmaf(xv, w0.w, s[3]);
        s[4] = fmaf(xv, w1.x, s[4]); s[5] = fmaf(xv, w1.y, s[5]);
        s[6] = fmaf(xv, w1.z, s[6]); s[7] = fmaf(xv, w1.w, s[7]);
    }
    #pragma unroll
    for (int off = 16; off > 0; off >>= 1)
        #pragma unroll
        for (int j = 0; j < 8; j++)
            s[j] += __shfl_xor_sync(0xffffffffu, s[j], off);
    if (lane == 0) {
        #pragma unroll
        for (int j = 0; j < 8; j++) s[j] += bg[j];
        int i1 = 0;
        #pragma unroll
        for (int j = 1; j < 8; j++) if (s[j] > s[i1]) i1 = j;  // strict > : earliest max (top_k tie rule)
        int i2 = -1; float b2 = -1e30f;
        #pragma unroll
        for (int j = 0; j < 8; j++) if (j != i1 && s[j] > b2) { b2 = s[j]; i2 = j; }
        float a1 = 1.f / (1.f + expf(b2 - s[i1]));
        g_m1[warp] = (unsigned char)(i1 + 1);
        g_m2[warp] = (unsigned char)(i2 + 1);
        g_a1[warp] = a1;
        g_a2[warp] = 1.f - a1;
    }
}

// ---------------- pack: per-(batch, memory>=1) stream compaction in time order ----------------
__global__ __launch_bounds__(256) void pack_kernel()
{
    int bm = blockIdx.x;          // 0..63
    int b  = bm >> 3;
    int m  = (bm & 7) + 1;        // 1..8
    __shared__ int wsum[8];
    int tid = threadIdx.x;
    int lane = tid & 31, w = tid >> 5;
    int base = 0;
    int segbase = (b*NM_ + m - 1) * T_;
    for (int t0 = 0; t0 < T_; t0 += 256) {
        int t = t0 + tid;
        int n = t*B_ + b;
        int sel = 0; float a = 0.f;
        int m1v = g_m1[n], m2v = g_m2[n];
        if      (m1v == m) { sel = 1; a = g_a1[n]; }
        else if (m2v == m) { sel = 1; a = g_a2[n]; }
        int incl = sel;
        #pragma unroll
        for (int off = 1; off < 32; off <<= 1) {
            int u = __shfl_up_sync(0xffffffffu, incl, off);
            if (lane >= off) incl += u;
        }
        if (lane == 31) wsum[w] = incl;
        __syncthreads();
        int woff = 0, tot = 0;
        #pragma unroll
        for (int i = 0; i < 8; i++) { int v = wsum[i]; tot += v; if (i < w) woff += v; }
        if (sel) {
            int pos = base + woff + incl - 1;
            g_tok[segbase + pos] = t;
            g_pa [segbase + pos] = a;
        }
        base += tot;
        __syncthreads();
    }
    if (tid == 0) g_cnt[b*NM_ + m - 1] = base;
}

// ---------------- SGEMM: C = A(MxK) * W(KxN) + bias, fp32, 128x128 tile ----------------
__global__ __launch_bounds__(256) void sgemm_kernel(const float* __restrict__ A,
                                                    const float* __restrict__ W,
                                                    const float* __restrict__ bias,
                                                    int N, int sel)
{
    __shared__ float As[8][128];   // transposed A tile
    __shared__ float Bs[8][128];
    float* Cb = (sel == 0) ? g_Q : (sel == 1) ? g_K : g_V;
    int tid = threadIdx.x;
    int tx = tid & 15, ty = tid >> 4;
    int m0 = blockIdx.y * 128;
    int n0 = blockIdx.x * 128;
    int aRow = tid >> 1;
    int aCol = (tid & 1) * 4;
    int bRow = tid >> 5;
    int bCol = (tid & 31) * 4;
    float acc[8][8];
    #pragma unroll
    for (int i = 0; i < 8; i++)
        #pragma unroll
        for (int j = 0; j < 8; j++) acc[i][j] = 0.f;

    for (int kt = 0; kt < D_; kt += 8) {
        float4 av = *reinterpret_cast<const float4*>(A + (size_t)(m0 + aRow)*D_ + kt + aCol);
        As[aCol+0][aRow] = av.x; As[aCol+1][aRow] = av.y;
        As[aCol+2][aRow] = av.z; As[aCol+3][aRow] = av.w;
        #pragma unroll
        for (int u = 0; u < 4; u++) {
            int c = n0 + bCol + u;
            Bs[bRow][bCol+u] = (c < N) ? W[(size_t)(kt + bRow)*N + c] : 0.f;
        }
        __syncthreads();
        #pragma unroll
        for (int kk = 0; kk < 8; kk++) {
            float4 t0 = *reinterpret_cast<const float4*>(&As[kk][ty*4]);
            float4 t1 = *reinterpret_cast<const float4*>(&As[kk][64 + ty*4]);
            float4 s0 = *reinterpret_cast<const float4*>(&Bs[kk][tx*4]);
            float4 s1 = *reinterpret_cast<const float4*>(&Bs[kk][64 + tx*4]);
            float a_[8] = {t0.x,t0.y,t0.z,t0.w,t1.x,t1.y,t1.z,t1.w};
            float b_[8] = {s0.x,s0.y,s0.z,s0.w,s1.x,s1.y,s1.z,s1.w};
            #pragma unroll
            for (int i = 0; i < 8; i++)
                #pragma unroll
                for (int j = 0; j < 8; j++)
                    acc[i][j] = fmaf(a_[i], b_[j], acc[i][j]);
        }
        __syncthreads();
    }
    #pragma unroll
    for (int i = 0; i < 8; i++) {
        int r = m0 + ((i < 4) ? (ty*4 + i) : (64 + ty*4 + i - 4));
        #pragma unroll
        for (int j = 0; j < 8; j++) {
            int c = n0 + ((j < 4) ? (tx*4 + j) : (64 + tx*4 + j - 4));
            if (c < N) Cb[(size_t)r*N + c] = acc[i][j] + bias[c];
        }
    }
}

// ---------------- per-chunk G = K^T V (64x64), rows gathered ----------------
__global__ __launch_bounds__(256) void chunk_g_kernel()
{
    int ci = blockIdx.x, m = blockIdx.y, b = blockIdx.z;
    int cnt = (m == 0) ? T_ : g_cnt[b*NM_ + m - 1];
    if ((ci << 6) >= cnt) return;
    int L = cnt - (ci << 6); if (L > 64) L = 64;
    __shared__ float Ks[64][64];
    __shared__ float Vs[64][64];
    int tid = threadIdx.x;
    {
        int r = tid >> 2, q4 = tid & 3;
        bool valid = r < L;
        const float *ks = g_K, *vs = g_V;
        if (valid) {
            int i = (ci << 6) + r;
            int t = (m == 0) ? i : g_tok[(b*NM_ + m - 1)*T_ + i];
            size_t n = (size_t)t*B_ + b;
            ks = g_K + n*NKV + m*HD;
            vs = g_V + n*NKV + m*HD;
        }
        #pragma unroll
        for (int j = 0; j < 4; j++) {
            int c = q4*16 + j*4;
            float4 kv = valid ? *reinterpret_cast<const float4*>(ks + c) : make_float4(0,0,0,0);
            float4 vv = valid ? *reinterpret_cast<const float4*>(vs + c) : make_float4(0,0,0,0);
            *reinterpret_cast<float4*>(&Ks[r][c]) = kv;
            *reinterpret_cast<float4*>(&Vs[r][c]) = vv;
        }
    }
    __syncthreads();
    int ai = tid & 15, cf = tid >> 4;
    float acc[4][4];
    #pragma unroll
    for (int i = 0; i < 4; i++)
        #pragma unroll
        for (int j = 0; j < 4; j++) acc[i][j] = 0.f;
    for (int rr = 0; rr < 64; rr++) {
        float4 ka = *reinterpret_cast<const float4*>(&Ks[rr][ai*4]);
        float4 vc = *reinterpret_cast<const float4*>(&Vs[rr][cf*4]);
        float a_[4] = {ka.x,ka.y,ka.z,ka.w};
        float v_[4] = {vc.x,vc.y,vc.z,vc.w};
        #pragma unroll
        for (int i = 0; i < 4; i++)
            #pragma unroll
            for (int j = 0; j < 4; j++)
                acc[i][j] = fmaf(a_[i], v_[j], acc[i][j]);
    }
    float* Gp = g_G + (size_t)((b*MP1 + m)*32 + ci) * 4096;
    #pragma unroll
    for (int i = 0; i < 4; i++) {
        float4 o = make_float4(acc[i][0], acc[i][1], acc[i][2], acc[i][3]);
        *reinterpret_cast<float4*>(Gp + (ai*4 + i)*64 + cf*4) = o;
    }
}

// ---------------- per-segment prefix over chunk states: S_c = M0 + sum_{c'<c} G_c' ----------------
__global__ __launch_bounds__(256) void prefix_kernel(const float* __restrict__ M0)
{
    int b = blockIdx.x / MP1, m = blockIdx.x % MP1;
    int cnt = (m == 0) ? T_ : g_cnt[b*NM_ + m - 1];
    int nch = (cnt + 63) >> 6;
    int tid = threadIdx.x;
    float st[16];
    #pragma unroll
    for (int k = 0; k < 16; k++) st[k] = M0[tid + 256*k];
    size_t base = (size_t)((b*MP1 + m) * 32) * 4096;
    for (int ci = 0; ci < nch; ci++) {
        size_t off = base + (size_t)ci * 4096;
        #pragma unroll
        for (int k = 0; k < 16; k++) {
            int idx = tid + 256*k;
            g_S[off + idx] = st[k];
            st[k] += g_G[off + idx];
        }
    }
}

// ---------------- per-chunk output: O = tril(Q K^T) V + Q S_c ; scatter alpha*O ----------------
__global__ __launch_bounds__(256) void chunk_o_kernel(float* __restrict__ out)
{
    int ci = blockIdx.x, m = blockIdx.y, b = blockIdx.z;
    int cnt = (m == 0) ? T_ : g_cnt[b*NM_ + m - 1];
    if ((ci << 6) >= cnt) return;
    int L = cnt - (ci << 6); if (L > 64) L = 64;

    __shared__ float Qt[64][64];   // [feat][row]
    __shared__ float KP[64][64];   // Kt [feat][tok], then Pt [tok][row]
    __shared__ float VS[64][64];   // V  [tok][feat], then S  [feat_in][feat_out]
    int tid = threadIdx.x;
    int segbase = (m == 0) ? 0 : (b*NM_ + m - 1)*T_;
    {
        int r = tid >> 2, q4 = tid & 3;
        bool valid = r < L;
        const float *qs = g_Q, *ks = g_K, *vs = g_V;
        if (valid) {
            int i = (ci << 6) + r;
            int t = (m == 0) ? i : g_tok[segbase + i];
            size_t n = (size_t)t*B_ + b;
            qs = g_Q + n*HD;
            ks = g_K + n*NKV + m*HD;
            vs = g_V + n*NKV + m*HD;
        }
        #pragma unroll
        for (int j = 0; j < 4; j++) {
            int c = q4*16 + j*4;
            float4 qv = valid ? *reinterpret_cast<const float4*>(qs + c) : make_float4(0,0,0,0);
            float4 kv = valid ? *reinterpret_cast<const float4*>(ks + c) : make_float4(0,0,0,0);
            float4 vv = valid ? *reinterpret_cast<const float4*>(vs + c) : make_float4(0,0,0,0);
            Qt[c+0][r] = qv.x; Qt[c+1][r] = qv.y; Qt[c+2][r] = qv.z; Qt[c+3][r] = qv.w;
            KP[c+0][r] = kv.x; KP[c+1][r] = kv.y; KP[c+2][r] = kv.z; KP[c+3][r] = kv.w;
            *reinterpret_cast<float4*>(&VS[r][c]) = vv;
        }
    }
    __syncthreads();

    int ri = tid & 15, cj = tid >> 4;
    int r0 = ri*4, c0 = cj*4;

    // stage 1: P[r][c] = q_r . k_c
    float p[4][4];
    #pragma unroll
    for (int i = 0; i < 4; i++)
        #pragma unroll
        for (int j = 0; j < 4; j++) p[i][j] = 0.f;
    for (int j = 0; j < 64; j++) {
        float4 qa = *reinterpret_cast<const float4*>(&Qt[j][r0]);
        float4 kc = *reinterpret_cast<const float4*>(&KP[j][c0]);
        float q_[4] = {qa.x,qa.y,qa.z,qa.w};
        float k_[4] = {kc.x,kc.y,kc.z,kc.w};
        #pragma unroll
        for (int i = 0; i < 4; i++)
            #pragma unroll
            for (int jj = 0; jj < 4; jj++)
                p[i][jj] = fmaf(q_[i], k_[jj], p[i][jj]);
    }
    __syncthreads();
    // write masked P transposed: Pt[tok c][row r], causal c <= r
    #pragma unroll
    for (int i = 0; i < 4; i++)
        #pragma unroll
        for (int jj = 0; jj < 4; jj++)
            KP[c0+jj][r0+i] = (c0+jj <= r0+i) ? p[i][jj] : 0.f;
    __syncthreads();

    // stage 2a: O = P V
    float o[4][4];
    #pragma unroll
    for (int i = 0; i < 4; i++)
        #pragma unroll
        for (int j = 0; j < 4; j++) o[i][j] = 0.f;
    for (int j = 0; j < 64; j++) {
        float4 pa = *reinterpret_cast<const float4*>(&KP[j][r0]);
        float4 vc = *reinterpret_cast<const float4*>(&VS[j][c0]);
        float p_[4] = {pa.x,pa.y,pa.z,pa.w};
        float v_[4] = {vc.x,vc.y,vc.z,vc.w};
        #pragma unroll
        for (int i = 0; i < 4; i++)
            #pragma unroll
            for (int jj = 0; jj < 4; jj++)
                o[i][jj] = fmaf(p_[i], v_[jj], o[i][jj]);
    }
    __syncthreads();
    // load S over V slot
    {
        int r = tid >> 2, q4 = tid & 3;
        const float* Sp = g_S + (size_t)((b*MP1 + m)*32 + ci) * 4096;
        #pragma unroll
        for (int j = 0; j < 4; j++) {
            int c = q4*16 + j*4;
            *reinterpret_cast<float4*>(&VS[r][c]) = *reinterpret_cast<const float4*>(Sp + r*64 + c);
        }
    }
    __syncthreads();
    // stage 2b: O += Q S
    for (int j = 0; j < 64; j++) {
        float4 qa = *reinterpret_cast<const float4*>(&Qt[j][r0]);
        float4 sc = *reinterpret_cast<const float4*>(&VS[j][c0]);
        float q_[4] = {qa.x,qa.y,qa.z,qa.w};
        float s_[4] = {sc.x,sc.y,sc.z,sc.w};
        #pragma unroll
        for (int i = 0; i < 4; i++)
            #pragma unroll
            for (int jj = 0; jj < 4; jj++)
                o[i][jj] = fmaf(q_[i], s_[jj], o[i][jj]);
    }

    // epilogue: out[t,b,:] += alpha * O[r,:]
    #pragma unroll
    for (int i = 0; i < 4; i++) {
        int r = r0 + i;
        if (r >= L) continue;
        int idx = (ci << 6) + r;
        int t; float alpha;
        if (m == 0) { t = idx; alpha = 1.f; }
        else        { t = g_tok[segbase + idx]; alpha = g_pa[segbase + idx]; }
        float* op = out + ((size_t)t*B_ + b)*HD + c0;
        atomicAdd(op + 0, alpha * o[i][0]);
        atomicAdd(op + 1, alpha * o[i][1]);
        atomicAdd(op + 2, alpha * o[i][2]);
        atomicAdd(op + 3, alpha * o[i][3]);
    }
}

// ---------------- launch ----------------
extern "C" void kernel_launch(void* const* d_in, const int* in_sizes, int n_in,
                              void* d_out, int out_size)
{
    const float* X  = (const float*)d_in[0];
    const float* M0 = (const float*)d_in[1];
    const float* Wq = (const float*)d_in[2];
    const float* bq = (const float*)d_in[3];
    const float* Wk = (const float*)d_in[4];
    const float* bk = (const float*)d_in[5];
    const float* Wv = (const float*)d_in[6];
    const float* bv = (const float*)d_in[7];
    const float* Wg = (const float*)d_in[8];
    const float* bg = (const float*)d_in[9];
    float* out = (float*)d_out;

    zero_kernel<<<(NT*HD + 255)/256, 256>>>(out, NT*HD);
    gate_kernel<<<NT/8, 256>>>(X, Wg, bg);
    pack_kernel<<<64, 256>>>();

    dim3 gq(1, NT/128);
    dim3 gk((NKV + 127)/128, NT/128);
    sgemm_kernel<<<gq, 256>>>(X, Wq, bq, HD, 0);
    sgemm_kernel<<<gk, 256>>>(X, Wk, bk, NKV, 1);
    sgemm_kernel<<<gk, 256>>>(X, Wv, bv, NKV, 2);

    chunk_g_kernel<<<dim3(32, MP1, B_), 256>>>();
    prefix_kernel<<<B_*MP1, 256>>>(M0);
    chunk_o_kernel<<<dim3(32, MP1, B_), 256>>>(out);
}

// round 4
// speedup vs baseline: 1.0006x; 1.0006x over previous
#include <cuda_runtime.h>
#include <math.h>

#define T_   2048
#define B_   8
#define D_   1024
#define HD   64      // d
#define NM_  8
#define MP1  9
#define NT   (T_*B_)     // 16384 tokens
#define NKV  576         // Mp1 * d

// ---------------- static device scratch (no runtime alloc allowed) ----------------
__device__ float g_Q[NT*HD];                       // 4 MB
__device__ float g_K[(size_t)NT*NKV];              // 37.75 MB
__device__ float g_V[(size_t)NT*NKV];              // 37.75 MB
#define NSLOT (B_*MP1*32)                          // 2304 chunk slots
__device__ float g_G[(size_t)NSLOT*HD*HD];         // per-chunk K^T V
__device__ float g_S[(size_t)NSLOT*HD*HD];         // per-chunk starting state
__device__ int   g_tok[B_*NM_*T_];                 // packed token time per (b,m)
__device__ float g_pa [B_*NM_*T_];                 // packed alpha per (b,m)
__device__ int   g_cnt[B_*NM_];                    // segment lengths
__device__ unsigned char g_m1[NT], g_m2[NT];
__device__ float g_a1[NT], g_a2[NT];

// ---------------- zero output ----------------
__global__ void zero_kernel(float* __restrict__ out, int n)
{
    int i = blockIdx.x * blockDim.x + threadIdx.x;
    if (i < n) out[i] = 0.f;
}

// ---------------- gating: logits -> top2 + normalized weights ----------------
// one warp per token; softmax is monotonic so top-k on logits; normalized
// softmax weights reduce to a1 = 1/(1+exp(l2-l1)).
__global__ void gate_kernel(const float* __restrict__ X,
                            const float* __restrict__ Wg,
                            const float* __restrict__ bg)
{
    int warp = (blockIdx.x * blockDim.x + threadIdx.x) >> 5;
    int lane = threadIdx.x & 31;
    if (warp >= NT) return;
    const float* x = X + (size_t)warp * D_;
    float s[8];
    #pragma unroll
    for (int j = 0; j < 8; j++) s[j] = 0.f;
    for (int i = lane; i < D_; i += 32) {
        float xv = x[i];
        float4 w0 = *reinterpret_cast<const float4*>(Wg + (size_t)i*8);
        float4 w1 = *reinterpret_cast<const float4*>(Wg + (size_t)i*8 + 4);
        s[0] = fmaf(xv, w0.x, s[0]); s[1] = fmaf(xv, w0.y, s[1]);
        s[2] = fmaf(xv, w0.z, s[2]); s[3] = fmaf(xv, w0.w, s[3]);
        s[4] = fmaf(xv, w1.x, s[4]); s[5] = fmaf(xv, w1.y, s[5]);
        s[6] = fmaf(xv, w1.z, s[6]); s[7] = fmaf(xv, w1.w, s[7]);
    }
    #pragma unroll
    for (int off = 16; off > 0; off >>= 1)
        #pragma unroll
        for (int j = 0; j < 8; j++)
            s[j] += __shfl_xor_sync(0xffffffffu, s[j], off);
    if (lane == 0) {
        #pragma unroll
        for (int j = 0; j < 8; j++) s[j] += bg[j];
        int i1 = 0;
        #pragma unroll
        for (int j = 1; j < 8; j++) if (s[j] > s[i1]) i1 = j;  // strict > : earliest max (top_k tie rule)
        int i2 = -1; float b2 = -1e30f;
        #pragma unroll
        for (int j = 0; j < 8; j++) if (j != i1 && s[j] > b2) { b2 = s[j]; i2 = j; }
        float a1 = 1.f / (1.f + expf(b2 - s[i1]));
        g_m1[warp] = (unsigned char)(i1 + 1);
        g_m2[warp] = (unsigned char)(i2 + 1);
        g_a1[warp] = a1;
        g_a2[warp] = 1.f - a1;
    }
}

// ---------------- pack: per-(batch, memory>=1) stream compaction in time order ----------------
__global__ __launch_bounds__(256) void pack_kernel()
{
    int bm = blockIdx.x;          // 0..63
    int b  = bm >> 3;
    int m  = (bm & 7) + 1;        // 1..8
    __shared__ int wsum[8];
    int tid = threadIdx.x;
    int lane = tid & 31, w = tid >> 5;
    int base = 0;
    int segbase = (b*NM_ + m - 1) * T_;
    for (int t0 = 0; t0 < T_; t0 += 256) {
        int t = t0 + tid;
        int n = t*B_ + b;
        int sel = 0; float a = 0.f;
        int m1v = g_m1[n], m2v = g_m2[n];
        if      (m1v == m) { sel = 1; a = g_a1[n]; }
        else if (m2v == m) { sel = 1; a = g_a2[n]; }
        int incl = sel;
        #pragma unroll
        for (int off = 1; off < 32; off <<= 1) {
            int u = __shfl_up_sync(0xffffffffu, incl, off);
            if (lane >= off) incl += u;
        }
        if (lane == 31) wsum[w] = incl;
        __syncthreads();
        int woff = 0, tot = 0;
        #pragma unroll
        for (int i = 0; i < 8; i++) { int v = wsum[i]; tot += v; if (i < w) woff += v; }
        if (sel) {
            int pos = base + woff + incl - 1;
            g_tok[segbase + pos] = t;
            g_pa [segbase + pos] = a;
        }
        base += tot;
        __syncthreads();
    }
    if (tid == 0) g_cnt[b*NM_ + m - 1] = base;
}

// ---------------- SGEMM: C = A(MxK) * W(KxN) + bias, fp32, 128x128 tile ----------------
__global__ __launch_bounds__(256) void sgemm_kernel(const float* __restrict__ A,
                                                    const float* __restrict__ W,
                                                    const float* __restrict__ bias,
                                                    int N, int sel)
{
    __shared__ float As[8][128];   // transposed A tile
    __shared__ float Bs[8][128];
    float* Cb = (sel == 0) ? g_Q : (sel == 1) ? g_K : g_V;
    int tid = threadIdx.x;
    int tx = tid & 15, ty = tid >> 4;
    int m0 = blockIdx.y * 128;
    int n0 = blockIdx.x * 128;
    int aRow = tid >> 1;
    int aCol = (tid & 1) * 4;
    int bRow = tid >> 5;
    int bCol = (tid & 31) * 4;
    float acc[8][8];
    #pragma unroll
    for (int i = 0; i < 8; i++)
        #pragma unroll
        for (int j = 0; j < 8; j++) acc[i][j] = 0.f;

    for (int kt = 0; kt < D_; kt += 8) {
        float4 av = *reinterpret_cast<const float4*>(A + (size_t)(m0 + aRow)*D_ + kt + aCol);
        As[aCol+0][aRow] = av.x; As[aCol+1][aRow] = av.y;
        As[aCol+2][aRow] = av.z; As[aCol+3][aRow] = av.w;
        #pragma unroll
        for (int u = 0; u < 4; u++) {
            int c = n0 + bCol + u;
            Bs[bRow][bCol+u] = (c < N) ? W[(size_t)(kt + bRow)*N + c] : 0.f;
        }
        __syncthreads();
        #pragma unroll
        for (int kk = 0; kk < 8; kk++) {
            float4 t0 = *reinterpret_cast<const float4*>(&As[kk][ty*4]);
            float4 t1 = *reinterpret_cast<const float4*>(&As[kk][64 + ty*4]);
            float4 s0 = *reinterpret_cast<const float4*>(&Bs[kk][tx*4]);
            float4 s1 = *reinterpret_cast<const float4*>(&Bs[kk][64 + tx*4]);
            float a_[8] = {t0.x,t0.y,t0.z,t0.w,t1.x,t1.y,t1.z,t1.w};
            float b_[8] = {s0.x,s0.y,s0.z,s0.w,s1.x,s1.y,s1.z,s1.w};
            #pragma unroll
            for (int i = 0; i < 8; i++)
                #pragma unroll
                for (int j = 0; j < 8; j++)
                    acc[i][j] = fmaf(a_[i], b_[j], acc[i][j]);
        }
        __syncthreads();
    }
    #pragma unroll
    for (int i = 0; i < 8; i++) {
        int r = m0 + ((i < 4) ? (ty*4 + i) : (64 + ty*4 + i - 4));
        #pragma unroll
        for (int j = 0; j < 8; j++) {
            int c = n0 + ((j < 4) ? (tx*4 + j) : (64 + tx*4 + j - 4));
            if (c < N) Cb[(size_t)r*N + c] = acc[i][j] + bias[c];
        }
    }
}

// ---------------- per-chunk G = K^T V (64x64), rows gathered ----------------
__global__ __launch_bounds__(256) void chunk_g_kernel()
{
    int ci = blockIdx.x, m = blockIdx.y, b = blockIdx.z;
    int cnt = (m == 0) ? T_ : g_cnt[b*NM_ + m - 1];
    if ((ci << 6) >= cnt) return;
    int L = cnt - (ci << 6); if (L > 64) L = 64;
    __shared__ float Ks[64][64];
    __shared__ float Vs[64][64];
    int tid = threadIdx.x;
    {
        int r = tid >> 2, q4 = tid & 3;
        bool valid = r < L;
        const float *ks = g_K, *vs = g_V;
        if (valid) {
            int i = (ci << 6) + r;
            int t = (m == 0) ? i : g_tok[(b*NM_ + m - 1)*T_ + i];
            size_t n = (size_t)t*B_ + b;
            ks = g_K + n*NKV + m*HD;
            vs = g_V + n*NKV + m*HD;
        }
        #pragma unroll
        for (int j = 0; j < 4; j++) {
            int c = q4*16 + j*4;
            float4 kv = valid ? *reinterpret_cast<const float4*>(ks + c) : make_float4(0,0,0,0);
            float4 vv = valid ? *reinterpret_cast<const float4*>(vs + c) : make_float4(0,0,0,0);
            *reinterpret_cast<float4*>(&Ks[r][c]) = kv;
            *reinterpret_cast<float4*>(&Vs[r][c]) = vv;
        }
    }
    __syncthreads();
    int ai = tid & 15, cf = tid >> 4;
    float acc[4][4];
    #pragma unroll
    for (int i = 0; i < 4; i++)
        #pragma unroll
        for (int j = 0; j < 4; j++) acc[i][j] = 0.f;
    for (int rr = 0; rr < 64; rr++) {
        float4 ka = *reinterpret_cast<const float4*>(&Ks[rr][ai*4]);
        float4 vc = *reinterpret_cast<const float4*>(&Vs[rr][cf*4]);
        float a_[4] = {ka.x,ka.y,ka.z,ka.w};
        float v_[4] = {vc.x,vc.y,vc.z,vc.w};
        #pragma unroll
        for (int i = 0; i < 4; i++)
            #pragma unroll
            for (int j = 0; j < 4; j++)
                acc[i][j] = fmaf(a_[i], v_[j], acc[i][j]);
    }
    float* Gp = g_G + (size_t)((b*MP1 + m)*32 + ci) * 4096;
    #pragma unroll
    for (int i = 0; i < 4; i++) {
        float4 o = make_float4(acc[i][0], acc[i][1], acc[i][2], acc[i][3]);
        *reinterpret_cast<float4*>(Gp + (ai*4 + i)*64 + cf*4) = o;
    }
}

// ---------------- per-segment prefix over chunk states: S_c = M0 + sum_{c'<c} G_c' ----------------
__global__ __launch_bounds__(256) void prefix_kernel(const float* __restrict__ M0)
{
    int b = blockIdx.x / MP1, m = blockIdx.x % MP1;
    int cnt = (m == 0) ? T_ : g_cnt[b*NM_ + m - 1];
    int nch = (cnt + 63) >> 6;
    int tid = threadIdx.x;
    float st[16];
    #pragma unroll
    for (int k = 0; k < 16; k++) st[k] = M0[tid + 256*k];
    size_t base = (size_t)((b*MP1 + m) * 32) * 4096;
    for (int ci = 0; ci < nch; ci++) {
        size_t off = base + (size_t)ci * 4096;
        #pragma unroll
        for (int k = 0; k < 16; k++) {
            int idx = tid + 256*k;
            g_S[off + idx] = st[k];
            st[k] += g_G[off + idx];
        }
    }
}

// ---------------- per-chunk output: O = tril(Q K^T) V + Q S_c ; scatter alpha*O ----------------
__global__ __launch_bounds__(256) void chunk_o_kernel(float* __restrict__ out)
{
    int ci = blockIdx.x, m = blockIdx.y, b = blockIdx.z;
    int cnt = (m == 0) ? T_ : g_cnt[b*NM_ + m - 1];
    if ((ci << 6) >= cnt) return;
    int L = cnt - (ci << 6); if (L > 64) L = 64;

    __shared__ float Qt[64][64];   // [feat][row]
    __shared__ float KP[64][64];   // Kt [feat][tok], then Pt [tok][row]
    __shared__ float VS[64][64];   // V  [tok][feat], then S  [feat_in][feat_out]
    int tid = threadIdx.x;
    int segbase = (m == 0) ? 0 : (b*NM_ + m - 1)*T_;
    {
        int r = tid >> 2, q4 = tid & 3;
        bool valid = r < L;
        const float *qs = g_Q, *ks = g_K, *vs = g_V;
        if (valid) {
            int i = (ci << 6) + r;
            int t = (m == 0) ? i : g_tok[segbase + i];
            size_t n = (size_t)t*B_ + b;
            qs = g_Q + n*HD;
            ks = g_K + n*NKV + m*HD;
            vs = g_V + n*NKV + m*HD;
        }
        #pragma unroll
        for (int j = 0; j < 4; j++) {
            int c = q4*16 + j*4;
            float4 qv = valid ? *reinterpret_cast<const float4*>(qs + c) : make_float4(0,0,0,0);
            float4 kv = valid ? *reinterpret_cast<const float4*>(ks + c) : make_float4(0,0,0,0);
            float4 vv = valid ? *reinterpret_cast<const float4*>(vs + c) : make_float4(0,0,0,0);
            Qt[c+0][r] = qv.x; Qt[c+1][r] = qv.y; Qt[c+2][r] = qv.z; Qt[c+3][r] = qv.w;
            KP[c+0][r] = kv.x; KP[c+1][r] = kv.y; KP[c+2][r] = kv.z; KP[c+3][r] = kv.w;
            *reinterpret_cast<float4*>(&VS[r][c]) = vv;
        }
    }
    __syncthreads();

    int ri = tid & 15, cj = tid >> 4;
    int r0 = ri*4, c0 = cj*4;

    // stage 1: P[r][c] = q_r . k_c
    float p[4][4];
    #pragma unroll
    for (int i = 0; i < 4; i++)
        #pragma unroll
        for (int j = 0; j < 4; j++) p[i][j] = 0.f;
    for (int j = 0; j < 64; j++) {
        float4 qa = *reinterpret_cast<const float4*>(&Qt[j][r0]);
        float4 kc = *reinterpret_cast<const float4*>(&KP[j][c0]);
        float q_[4] = {qa.x,qa.y,qa.z,qa.w};
        float k_[4] = {kc.x,kc.y,kc.z,kc.w};
        #pragma unroll
        for (int i = 0; i < 4; i++)
            #pragma unroll
            for (int jj = 0; jj < 4; jj++)
                p[i][jj] = fmaf(q_[i], k_[jj], p[i][jj]);
    }
    __syncthreads();
    // write masked P transposed: Pt[tok c][row r], causal c <= r
    #pragma unroll
    for (int i = 0; i < 4; i++)
        #pragma unroll
        for (int jj = 0; jj < 4; jj++)
            KP[c0+jj][r0+i] = (c0+jj <= r0+i) ? p[i][jj] : 0.f;
    __syncthreads();

    // stage 2a: O = P V
    float o[4][4];
    #pragma unroll
    for (int i = 0; i < 4; i++)
        #pragma unroll
        for (int j = 0; j < 4; j++) o[i][j] = 0.f;
    for (int j = 0; j < 64; j++) {
        float4 pa = *reinterpret_cast<const float4*>(&KP[j][r0]);
        float4 vc = *reinterpret_cast<const float4*>(&VS[j][c0]);
        float p_[4] = {pa.x,pa.y,pa.z,pa.w};
        float v_[4] = {vc.x,vc.y,vc.z,vc.w};
        #pragma unroll
        for (int i = 0; i < 4; i++)
            #pragma unroll
            for (int jj = 0; jj < 4; jj++)
                o[i][jj] = fmaf(p_[i], v_[jj], o[i][jj]);
    }
    __syncthreads();
    // load S over V slot
    {
        int r = tid >> 2, q4 = tid & 3;
        const float* Sp = g_S + (size_t)((b*MP1 + m)*32 + ci) * 4096;
        #pragma unroll
        for (int j = 0; j < 4; j++) {
            int c = q4*16 + j*4;
            *reinterpret_cast<float4*>(&VS[r][c]) = *reinterpret_cast<const float4*>(Sp + r*64 + c);
        }
    }
    __syncthreads();
    // stage 2b: O += Q S
    for (int j = 0; j < 64; j++) {
        float4 qa = *reinterpret_cast<const float4*>(&Qt[j][r0]);
        float4 sc = *reinterpret_cast<const float4*>(&VS[j][c0]);
        float q_[4] = {qa.x,qa.y,qa.z,qa.w};
        float s_[4] = {sc.x,sc.y,sc.z,sc.w};
        #pragma unroll
        for (int i = 0; i < 4; i++)
            #pragma unroll
            for (int jj = 0; jj < 4; jj++)
                o[i][jj] = fmaf(q_[i], s_[jj], o[i][jj]);
    }

    // epilogue: out[t,b,:] += alpha * O[r,:]
    #pragma unroll
    for (int i = 0; i < 4; i++) {
        int r = r0 + i;
        if (r >= L) continue;
        int idx = (ci << 6) + r;
        int t; float alpha;
        if (m == 0) { t = idx; alpha = 1.f; }
        else        { t = g_tok[segbase + idx]; alpha = g_pa[segbase + idx]; }
        float* op = out + ((size_t)t*B_ + b)*HD + c0;
        atomicAdd(op + 0, alpha * o[i][0]);
        atomicAdd(op + 1, alpha * o[i][1]);
        atomicAdd(op + 2, alpha * o[i][2]);
        atomicAdd(op + 3, alpha * o[i][3]);
    }
}

// ---------------- launch ----------------
extern "C" void kernel_launch(void* const* d_in, const int* in_sizes, int n_in,
                              void* d_out, int out_size)
{
    const float* X  = (const float*)d_in[0];
    const float* M0 = (const float*)d_in[1];
    const float* Wq = (const float*)d_in[2];
    const float* bq = (const float*)d_in[3];
    const float* Wk = (const float*)d_in[4];
    const float* bk = (const float*)d_in[5];
    const float* Wv = (const float*)d_in[6];
    const float* bv = (const float*)d_in[7];
    const float* Wg = (const float*)d_in[8];
    const float* bg = (const float*)d_in[9];
    float* out = (float*)d_out;

    zero_kernel<<<(NT*HD + 255)/256, 256>>>(out, NT*HD);
    gate_kernel<<<NT/8, 256>>>(X, Wg, bg);
    pack_kernel<<<64, 256>>>();

    dim3 gq(1, NT/128);
    dim3 gk((NKV + 127)/128, NT/128);
    sgemm_kernel<<<gq, 256>>>(X, Wq, bq, HD, 0);
    sgemm_kernel<<<gk, 256>>>(X, Wk, bk, NKV, 1);
    sgemm_kernel<<<gk, 256>>>(X, Wv, bv, NKV, 2);

    chunk_g_kernel<<<dim3(32, MP1, B_), 256>>>();
    prefix_kernel<<<B_*MP1, 256>>>(M0);
    chunk_o_kernel<<<dim3(32, MP1, B_), 256>>>(out);
}

// round 5
// speedup vs baseline: 2.6760x; 2.6744x over previous
#include <cuda_runtime.h>
#include <math.h>

#define T_   2048
#define B_   8
#define D_   1024
#define HD   64      // d
#define NM_  8
#define MP1  9
#define NT   (T_*B_)     // 16384 tokens
#define NKV  576         // Mp1 * d

// ---------------- static device scratch ----------------
__device__ float g_Q[NT*HD];                                // 4 MB
__device__ float g_Kp[(size_t)B_*MP1*T_*HD];                // packed K per (b,m): 36 MB
__device__ float g_Vp[(size_t)B_*MP1*T_*HD];                // packed V per (b,m): 36 MB
#define NSLOT (B_*MP1*32)                                   // 2304 chunk slots
__device__ float g_G[(size_t)NSLOT*HD*HD];                  // per-chunk K^T V
__device__ float g_S[(size_t)NSLOT*HD*HD];                  // per-chunk starting state
__device__ int   g_tok[B_*NM_*T_];                          // packed token time per (b,m>=1)
__device__ float g_pa [B_*NM_*T_];                          // packed alpha per (b,m>=1)
__device__ int   g_cnt[B_*NM_];                             // segment lengths
__device__ unsigned char g_m1[NT], g_m2[NT];
__device__ float g_a1[NT], g_a2[NT];

// ---------------- zero output ----------------
__global__ void zero_kernel(float* __restrict__ out, int n)
{
    int i = blockIdx.x * blockDim.x + threadIdx.x;
    if (i < n) out[i] = 0.f;
}

// ---------------- gating ----------------
__global__ void gate_kernel(const float* __restrict__ X,
                            const float* __restrict__ Wg,
                            const float* __restrict__ bg)
{
    int warp = (blockIdx.x * blockDim.x + threadIdx.x) >> 5;
    int lane = threadIdx.x & 31;
    if (warp >= NT) return;
    const float* x = X + (size_t)warp * D_;
    float s[8];
    #pragma unroll
    for (int j = 0; j < 8; j++) s[j] = 0.f;
    for (int i = lane; i < D_; i += 32) {
        float xv = x[i];
        float4 w0 = *reinterpret_cast<const float4*>(Wg + (size_t)i*8);
        float4 w1 = *reinterpret_cast<const float4*>(Wg + (size_t)i*8 + 4);
        s[0] = fmaf(xv, w0.x, s[0]); s[1] = fmaf(xv, w0.y, s[1]);
        s[2] = fmaf(xv, w0.z, s[2]); s[3] = fmaf(xv, w0.w, s[3]);
        s[4] = fmaf(xv, w1.x, s[4]); s[5] = fmaf(xv, w1.y, s[5]);
        s[6] = fmaf(xv, w1.z, s[6]); s[7] = fmaf(xv, w1.w, s[7]);
    }
    #pragma unroll
    for (int off = 16; off > 0; off >>= 1)
        #pragma unroll
        for (int j = 0; j < 8; j++)
            s[j] += __shfl_xor_sync(0xffffffffu, s[j], off);
    if (lane == 0) {
        #pragma unroll
        for (int j = 0; j < 8; j++) s[j] += bg[j];
        int i1 = 0;
        #pragma unroll
        for (int j = 1; j < 8; j++) if (s[j] > s[i1]) i1 = j;
        int i2 = -1; float b2 = -1e30f;
        #pragma unroll
        for (int j = 0; j < 8; j++) if (j != i1 && s[j] > b2) { b2 = s[j]; i2 = j; }
        float a1 = 1.f / (1.f + expf(b2 - s[i1]));
        g_m1[warp] = (unsigned char)(i1 + 1);
        g_m2[warp] = (unsigned char)(i2 + 1);
        g_a1[warp] = a1;
        g_a2[warp] = 1.f - a1;
    }
}

// ---------------- pack ----------------
__global__ __launch_bounds__(256) void pack_kernel()
{
    int bm = blockIdx.x;          // 0..63
    int b  = bm >> 3;
    int m  = (bm & 7) + 1;        // 1..8
    __shared__ int wsum[8];
    int tid = threadIdx.x;
    int lane = tid & 31, w = tid >> 5;
    int base = 0;
    int segbase = (b*NM_ + m - 1) * T_;
    for (int t0 = 0; t0 < T_; t0 += 256) {
        int t = t0 + tid;
        int n = t*B_ + b;
        int sel = 0; float a = 0.f;
        int m1v = g_m1[n], m2v = g_m2[n];
        if      (m1v == m) { sel = 1; a = g_a1[n]; }
        else if (m2v == m) { sel = 1; a = g_a2[n]; }
        int incl = sel;
        #pragma unroll
        for (int off = 1; off < 32; off <<= 1) {
            int u = __shfl_up_sync(0xffffffffu, incl, off);
            if (lane >= off) incl += u;
        }
        if (lane == 31) wsum[w] = incl;
        __syncthreads();
        int woff = 0, tot = 0;
        #pragma unroll
        for (int i = 0; i < 8; i++) { int v = wsum[i]; tot += v; if (i < w) woff += v; }
        if (sel) {
            int pos = base + woff + incl - 1;
            g_tok[segbase + pos] = t;
            g_pa [segbase + pos] = a;
        }
        base += tot;
        __syncthreads();
    }
    if (tid == 0) g_cnt[b*NM_ + m - 1] = base;
}

// ---------------- packed K|V projection: per (b,m) segment, gathered rows ----------------
// Tile: 128 packed rows x (64 K cols | 64 V cols), K-dim = 1024, double-buffered.
__global__ __launch_bounds__(256, 2) void proj_kv_kernel(
    const float* __restrict__ X,
    const float* __restrict__ Wk, const float* __restrict__ bk,
    const float* __restrict__ Wv, const float* __restrict__ bv)
{
    int ci = blockIdx.x, m = blockIdx.y, b = blockIdx.z;
    int cnt = (m == 0) ? T_ : g_cnt[b*NM_ + m - 1];
    int r0 = ci << 7;
    if (r0 >= cnt) return;
    int L = cnt - r0; if (L > 128) L = 128;

    __shared__ float As[2][8][128];
    __shared__ float Bs[2][8][128];
    __shared__ int rowIdx[128];
    int tid = threadIdx.x;
    int segbase = (b*NM_ + m - 1) * T_;   // valid only for m>=1
    if (tid < 128) {
        int t = 0;
        if (tid < L) t = (m == 0) ? (r0 + tid) : g_tok[segbase + r0 + tid];
        rowIdx[tid] = t*B_ + b;
    }
    __syncthreads();

    int aRow = tid >> 1, aCol = (tid & 1) * 4;
    int bRow = tid >> 5;                 // 0..7
    int bHalf = (tid >> 4) & 1;          // 0 -> K cols, 1 -> V cols
    int bCol = (tid & 15) * 4;           // 0..60
    const float* Wsrc = bHalf ? Wv : Wk;
    const float* aPtr = X + (size_t)rowIdx[aRow]*D_ + aCol;
    const float* bPtr = Wsrc + (size_t)bRow*NKV + m*HD + bCol;

    int tx = tid & 15, ty = tid >> 4;
    float acc[8][8];
    #pragma unroll
    for (int i = 0; i < 8; i++)
        #pragma unroll
        for (int j = 0; j < 8; j++) acc[i][j] = 0.f;

    // prologue: stage kt=0
    float4 aReg = *reinterpret_cast<const float4*>(aPtr);
    float4 bReg = *reinterpret_cast<const float4*>(bPtr);
    As[0][aCol+0][aRow] = aReg.x; As[0][aCol+1][aRow] = aReg.y;
    As[0][aCol+2][aRow] = aReg.z; As[0][aCol+3][aRow] = aReg.w;
    *reinterpret_cast<float4*>(&Bs[0][bRow][bHalf*64 + bCol]) = bReg;
    __syncthreads();

    int cur = 0;
    for (int kt = 0; kt < D_; kt += 8) {
        if (kt + 8 < D_) {
            aReg = *reinterpret_cast<const float4*>(aPtr + kt + 8);
            bReg = *reinterpret_cast<const float4*>(bPtr + (size_t)(kt + 8)*NKV);
        }
        #pragma unroll
        for (int kk = 0; kk < 8; kk++) {
            float4 t0 = *reinterpret_cast<const float4*>(&As[cur][kk][ty*4]);
            float4 t1 = *reinterpret_cast<const float4*>(&As[cur][kk][64 + ty*4]);
            float4 s0 = *reinterpret_cast<const float4*>(&Bs[cur][kk][tx*4]);
            float4 s1 = *reinterpret_cast<const float4*>(&Bs[cur][kk][64 + tx*4]);
            float a_[8] = {t0.x,t0.y,t0.z,t0.w,t1.x,t1.y,t1.z,t1.w};
            float b_[8] = {s0.x,s0.y,s0.z,s0.w,s1.x,s1.y,s1.z,s1.w};
            #pragma unroll
            for (int i = 0; i < 8; i++)
                #pragma unroll
                for (int j = 0; j < 8; j++)
                    acc[i][j] = fmaf(a_[i], b_[j], acc[i][j]);
        }
        if (kt + 8 < D_) {
            int nxt = cur ^ 1;
            As[nxt][aCol+0][aRow] = aReg.x; As[nxt][aCol+1][aRow] = aReg.y;
            As[nxt][aCol+2][aRow] = aReg.z; As[nxt][aCol+3][aRow] = aReg.w;
            *reinterpret_cast<float4*>(&Bs[nxt][bRow][bHalf*64 + bCol]) = bReg;
        }
        __syncthreads();
        cur ^= 1;
    }

    size_t segKV = ((size_t)(b*MP1 + m)*T_ + r0) * HD;
    #pragma unroll
    for (int i = 0; i < 8; i++) {
        int r = (i < 4) ? (ty*4 + i) : (64 + ty*4 + i - 4);
        if (r >= L) continue;
        #pragma unroll
        for (int j = 0; j < 8; j++) {
            int c = (j < 4) ? (tx*4 + j) : (64 + tx*4 + j - 4);
            float v = acc[i][j];
            if (c < 64) g_Kp[segKV + (size_t)r*HD + c]        = v + bk[m*HD + c];
            else        g_Vp[segKV + (size_t)r*HD + (c - 64)] = v + bv[m*HD + (c - 64)];
        }
    }
}

// ---------------- Q projection: 128 rows x 64 cols, double-buffered ----------------
__global__ __launch_bounds__(256, 2) void proj_q_kernel(
    const float* __restrict__ X,
    const float* __restrict__ Wq, const float* __restrict__ bq)
{
    __shared__ float As[2][8][128];
    __shared__ float Bs[2][8][64];
    int tid = threadIdx.x;
    int m0 = blockIdx.x * 128;

    int aRow = tid >> 1, aCol = (tid & 1) * 4;
    const float* aPtr = X + (size_t)(m0 + aRow)*D_ + aCol;
    int bRow = tid >> 4;                 // 0..15 (only tid<128 loads)
    int bCol = (tid & 15) * 4;
    const float* bPtr = Wq + (size_t)bRow*HD + bCol;
    bool bAct = (tid < 128);

    int tx = tid & 15, ty = tid >> 4;
    float acc[8][4];
    #pragma unroll
    for (int i = 0; i < 8; i++)
        #pragma unroll
        for (int j = 0; j < 4; j++) acc[i][j] = 0.f;

    float4 aReg = *reinterpret_cast<const float4*>(aPtr);
    float4 bReg = bAct ? *reinterpret_cast<const float4*>(bPtr) : make_float4(0,0,0,0);
    As[0][aCol+0][aRow] = aReg.x; As[0][aCol+1][aRow] = aReg.y;
    As[0][aCol+2][aRow] = aReg.z; As[0][aCol+3][aRow] = aReg.w;
    if (bAct) *reinterpret_cast<float4*>(&Bs[0][bRow & 7][bCol]) = bReg;   // bRow<8 for tid<128
    __syncthreads();

    int cur = 0;
    for (int kt = 0; kt < D_; kt += 8) {
        if (kt + 8 < D_) {
            aReg = *reinterpret_cast<const float4*>(aPtr + kt + 8);
            if (bAct) bReg = *reinterpret_cast<const float4*>(bPtr + (size_t)(kt + 8)*HD);
        }
        #pragma unroll
        for (int kk = 0; kk < 8; kk++) {
            float4 t0 = *reinterpret_cast<const float4*>(&As[cur][kk][ty*4]);
            float4 t1 = *reinterpret_cast<const float4*>(&As[cur][kk][64 + ty*4]);
            float4 s0 = *reinterpret_cast<const float4*>(&Bs[cur][kk][tx*4]);
            float a_[8] = {t0.x,t0.y,t0.z,t0.w,t1.x,t1.y,t1.z,t1.w};
            float b_[4] = {s0.x,s0.y,s0.z,s0.w};
            #pragma unroll
            for (int i = 0; i < 8; i++)
                #pragma unroll
                for (int j = 0; j < 4; j++)
                    acc[i][j] = fmaf(a_[i], b_[j], acc[i][j]);
        }
        if (kt + 8 < D_) {
            int nxt = cur ^ 1;
            As[nxt][aCol+0][aRow] = aReg.x; As[nxt][aCol+1][aRow] = aReg.y;
            As[nxt][aCol+2][aRow] = aReg.z; As[nxt][aCol+3][aRow] = aReg.w;
            if (bAct) *reinterpret_cast<float4*>(&Bs[nxt][bRow & 7][bCol]) = bReg;
        }
        __syncthreads();
        cur ^= 1;
    }

    #pragma unroll
    for (int i = 0; i < 8; i++) {
        int r = m0 + ((i < 4) ? (ty*4 + i) : (64 + ty*4 + i - 4));
        #pragma unroll
        for (int j = 0; j < 4; j++) {
            int c = tx*4 + j;
            g_Q[(size_t)r*HD + c] = acc[i][j] + bq[c];
        }
    }
}

// ---------------- per-chunk G = K^T V (64x64), packed contiguous rows ----------------
__global__ __launch_bounds__(256) void chunk_g_kernel()
{
    int ci = blockIdx.x, m = blockIdx.y, b = blockIdx.z;
    int cnt = (m == 0) ? T_ : g_cnt[b*NM_ + m - 1];
    if ((ci << 6) >= cnt) return;
    int L = cnt - (ci << 6); if (L > 64) L = 64;
    __shared__ float Ks[64][64];
    __shared__ float Vs[64][64];
    int tid = threadIdx.x;
    size_t segp = ((size_t)(b*MP1 + m)*T_ + (ci << 6)) * HD;
    {
        int r = tid >> 2, q4 = tid & 3;
        bool valid = r < L;
        #pragma unroll
        for (int j = 0; j < 4; j++) {
            int c = q4*16 + j*4;
            float4 kv = valid ? *reinterpret_cast<const float4*>(g_Kp + segp + (size_t)r*HD + c) : make_float4(0,0,0,0);
            float4 vv = valid ? *reinterpret_cast<const float4*>(g_Vp + segp + (size_t)r*HD + c) : make_float4(0,0,0,0);
            *reinterpret_cast<float4*>(&Ks[r][c]) = kv;
            *reinterpret_cast<float4*>(&Vs[r][c]) = vv;
        }
    }
    __syncthreads();
    int ai = tid & 15, cf = tid >> 4;
    float acc[4][4];
    #pragma unroll
    for (int i = 0; i < 4; i++)
        #pragma unroll
        for (int j = 0; j < 4; j++) acc[i][j] = 0.f;
    for (int rr = 0; rr < 64; rr++) {
        float4 ka = *reinterpret_cast<const float4*>(&Ks[rr][ai*4]);
        float4 vc = *reinterpret_cast<const float4*>(&Vs[rr][cf*4]);
        float a_[4] = {ka.x,ka.y,ka.z,ka.w};
        float v_[4] = {vc.x,vc.y,vc.z,vc.w};
        #pragma unroll
        for (int i = 0; i < 4; i++)
            #pragma unroll
            for (int j = 0; j < 4; j++)
                acc[i][j] = fmaf(a_[i], v_[j], acc[i][j]);
    }
    float* Gp = g_G + (size_t)((b*MP1 + m)*32 + ci) * 4096;
    #pragma unroll
    for (int i = 0; i < 4; i++) {
        float4 o = make_float4(acc[i][0], acc[i][1], acc[i][2], acc[i][3]);
        *reinterpret_cast<float4*>(Gp + (ai*4 + i)*64 + cf*4) = o;
    }
}

// ---------------- per-segment prefix over chunk states ----------------
__global__ __launch_bounds__(256) void prefix_kernel(const float* __restrict__ M0)
{
    int b = blockIdx.x / MP1, m = blockIdx.x % MP1;
    int cnt = (m == 0) ? T_ : g_cnt[b*NM_ + m - 1];
    int nch = (cnt + 63) >> 6;
    int tid = threadIdx.x;
    float st[16];
    #pragma unroll
    for (int k = 0; k < 16; k++) st[k] = M0[tid + 256*k];
    size_t base = (size_t)((b*MP1 + m) * 32) * 4096;
    for (int ci = 0; ci < nch; ci++) {
        size_t off = base + (size_t)ci * 4096;
        #pragma unroll
        for (int k = 0; k < 16; k++) {
            int idx = tid + 256*k;
            g_S[off + idx] = st[k];
            st[k] += g_G[off + idx];
        }
    }
}

// ---------------- per-chunk output: O = tril(Q K^T) V + Q S_c ; scatter alpha*O ----------------
__global__ __launch_bounds__(256) void chunk_o_kernel(float* __restrict__ out)
{
    int ci = blockIdx.x, m = blockIdx.y, b = blockIdx.z;
    int cnt = (m == 0) ? T_ : g_cnt[b*NM_ + m - 1];
    if ((ci << 6) >= cnt) return;
    int L = cnt - (ci << 6); if (L > 64) L = 64;

    __shared__ float Qt[64][64];   // [feat][row]
    __shared__ float KP[64][64];   // Kt [feat][tok], then Pt [tok][row]
    __shared__ float VS[64][64];   // V  [tok][feat], then S  [feat_in][feat_out]
    int tid = threadIdx.x;
    int segbase = (m == 0) ? 0 : (b*NM_ + m - 1)*T_;
    size_t segp = ((size_t)(b*MP1 + m)*T_ + (ci << 6)) * HD;
    {
        int r = tid >> 2, q4 = tid & 3;
        bool valid = r < L;
        const float* qs = g_Q;
        if (valid) {
            int i = (ci << 6) + r;
            int t = (m == 0) ? i : g_tok[segbase + i];
            qs = g_Q + ((size_t)t*B_ + b)*HD;
        }
        #pragma unroll
        for (int j = 0; j < 4; j++) {
            int c = q4*16 + j*4;
            float4 qv = valid ? *reinterpret_cast<const float4*>(qs + c) : make_float4(0,0,0,0);
            float4 kv = valid ? *reinterpret_cast<const float4*>(g_Kp + segp + (size_t)r*HD + c) : make_float4(0,0,0,0);
            float4 vv = valid ? *reinterpret_cast<const float4*>(g_Vp + segp + (size_t)r*HD + c) : make_float4(0,0,0,0);
            Qt[c+0][r] = qv.x; Qt[c+1][r] = qv.y; Qt[c+2][r] = qv.z; Qt[c+3][r] = qv.w;
            KP[c+0][r] = kv.x; KP[c+1][r] = kv.y; KP[c+2][r] = kv.z; KP[c+3][r] = kv.w;
            *reinterpret_cast<float4*>(&VS[r][c]) = vv;
        }
    }
    __syncthreads();

    int ri = tid & 15, cj = tid >> 4;
    int r0 = ri*4, c0 = cj*4;

    // stage 1: P[r][c] = q_r . k_c
    float p[4][4];
    #pragma unroll
    for (int i = 0; i < 4; i++)
        #pragma unroll
        for (int j = 0; j < 4; j++) p[i][j] = 0.f;
    for (int j = 0; j < 64; j++) {
        float4 qa = *reinterpret_cast<const float4*>(&Qt[j][r0]);
        float4 kc = *reinterpret_cast<const float4*>(&KP[j][c0]);
        float q_[4] = {qa.x,qa.y,qa.z,qa.w};
        float k_[4] = {kc.x,kc.y,kc.z,kc.w};
        #pragma unroll
        for (int i = 0; i < 4; i++)
            #pragma unroll
            for (int jj = 0; jj < 4; jj++)
                p[i][jj] = fmaf(q_[i], k_[jj], p[i][jj]);
    }
    __syncthreads();
    #pragma unroll
    for (int i = 0; i < 4; i++)
        #pragma unroll
        for (int jj = 0; jj < 4; jj++)
            KP[c0+jj][r0+i] = (c0+jj <= r0+i) ? p[i][jj] : 0.f;
    __syncthreads();

    // stage 2a: O = P V
    float o[4][4];
    #pragma unroll
    for (int i = 0; i < 4; i++)
        #pragma unroll
        for (int j = 0; j < 4; j++) o[i][j] = 0.f;
    for (int j = 0; j < 64; j++) {
        float4 pa = *reinterpret_cast<const float4*>(&KP[j][r0]);
        float4 vc = *reinterpret_cast<const float4*>(&VS[j][c0]);
        float p_[4] = {pa.x,pa.y,pa.z,pa.w};
        float v_[4] = {vc.x,vc.y,vc.z,vc.w};
        #pragma unroll
        for (int i = 0; i < 4; i++)
            #pragma unroll
            for (int jj = 0; jj < 4; jj++)
                o[i][jj] = fmaf(p_[i], v_[jj], o[i][jj]);
    }
    __syncthreads();
    {
        int r = tid >> 2, q4 = tid & 3;
        const float* Sp = g_S + (size_t)((b*MP1 + m)*32 + ci) * 4096;
        #pragma unroll
        for (int j = 0; j < 4; j++) {
            int c = q4*16 + j*4;
            *reinterpret_cast<float4*>(&VS[r][c]) = *reinterpret_cast<const float4*>(Sp + r*64 + c);
        }
    }
    __syncthreads();
    // stage 2b: O += Q S
    for (int j = 0; j < 64; j++) {
        float4 qa = *reinterpret_cast<const float4*>(&Qt[j][r0]);
        float4 sc = *reinterpret_cast<const float4*>(&VS[j][c0]);
        float q_[4] = {qa.x,qa.y,qa.z,qa.w};
        float s_[4] = {sc.x,sc.y,sc.z,sc.w};
        #pragma unroll
        for (int i = 0; i < 4; i++)
            #pragma unroll
            for (int jj = 0; jj < 4; jj++)
                o[i][jj] = fmaf(q_[i], s_[jj], o[i][jj]);
    }

    // epilogue: out[t,b,:] += alpha * O[r,:]
    #pragma unroll
    for (int i = 0; i < 4; i++) {
        int r = r0 + i;
        if (r >= L) continue;
        int idx = (ci << 6) + r;
        int t; float alpha;
        if (m == 0) { t = idx; alpha = 1.f; }
        else        { t = g_tok[segbase + idx]; alpha = g_pa[segbase + idx]; }
        float* op = out + ((size_t)t*B_ + b)*HD + c0;
        atomicAdd(op + 0, alpha * o[i][0]);
        atomicAdd(op + 1, alpha * o[i][1]);
        atomicAdd(op + 2, alpha * o[i][2]);
        atomicAdd(op + 3, alpha * o[i][3]);
    }
}

// ---------------- launch ----------------
extern "C" void kernel_launch(void* const* d_in, const int* in_sizes, int n_in,
                              void* d_out, int out_size)
{
    const float* X  = (const float*)d_in[0];
    const float* M0 = (const float*)d_in[1];
    const float* Wq = (const float*)d_in[2];
    const float* bq = (const float*)d_in[3];
    const float* Wk = (const float*)d_in[4];
    const float* bk = (const float*)d_in[5];
    const float* Wv = (const float*)d_in[6];
    const float* bv = (const float*)d_in[7];
    const float* Wg = (const float*)d_in[8];
    const float* bg = (const float*)d_in[9];
    float* out = (float*)d_out;

    zero_kernel<<<(NT*HD + 255)/256, 256>>>(out, NT*HD);
    gate_kernel<<<NT/8, 256>>>(X, Wg, bg);
    pack_kernel<<<64, 256>>>();

    proj_q_kernel<<<NT/128, 256>>>(X, Wq, bq);
    proj_kv_kernel<<<dim3(16, MP1, B_), 256>>>(X, Wk, bk, Wv, bv);

    chunk_g_kernel<<<dim3(32, MP1, B_), 256>>>();
    prefix_kernel<<<B_*MP1, 256>>>(M0);
    chunk_o_kernel<<<dim3(32, MP1, B_), 256>>>(out);
}

// round 6
// speedup vs baseline: 3.9308x; 1.4689x over previous
#include <cuda_runtime.h>
#include <math.h>

#define T_   2048
#define B_   8
#define D_   1024
#define HD   64      // d
#define NM_  8
#define MP1  9
#define NT   (T_*B_)     // 16384 tokens
#define NKV  576         // Mp1 * d

// ---------------- static device scratch ----------------
__device__ float g_Q[NT*HD];                                // 4 MB  (row-major [token, d]; token = t*B+b)
__device__ float g_Kp[(size_t)B_*MP1*T_*HD];                // packed K per (b,m): 36 MB
__device__ float g_Vp[(size_t)B_*MP1*T_*HD];                // packed V per (b,m): 36 MB
#define NSLOT (B_*MP1*32)                                   // 2304 chunk slots
__device__ float g_G[(size_t)NSLOT*HD*HD];                  // per-chunk K^T V
__device__ float g_S[(size_t)NSLOT*HD*HD];                  // per-chunk starting state
__device__ int   g_tok[B_*NM_*T_];                          // packed token time per (b,m>=1)
__device__ float g_pa [B_*NM_*T_];                          // packed alpha per (b,m>=1)
__device__ int   g_cnt[B_*NM_];                             // segment lengths
__device__ unsigned char g_m1[NT], g_m2[NT];
__device__ float g_a1[NT], g_a2[NT];

// ---------------- tf32 mma helpers ----------------
__device__ __forceinline__ unsigned f2tf32(float f) {
    unsigned u;
    asm("cvt.rna.tf32.f32 %0, %1;" : "=r"(u) : "f"(f));
    return u;
}
__device__ __forceinline__ void mma_tf32(float* c,
    unsigned a0, unsigned a1, unsigned a2, unsigned a3,
    unsigned b0, unsigned b1)
{
    asm volatile(
        "mma.sync.aligned.m16n8k8.row.col.f32.tf32.tf32.f32 "
        "{%0,%1,%2,%3}, {%4,%5,%6,%7}, {%8,%9}, {%0,%1,%2,%3};"
        : "+f"(c[0]), "+f"(c[1]), "+f"(c[2]), "+f"(c[3])
        : "r"(a0), "r"(a1), "r"(a2), "r"(a3), "r"(b0), "r"(b1));
}

// ---------------- zero output ----------------
__global__ void zero_kernel(float* __restrict__ out, int n)
{
    int i = blockIdx.x * blockDim.x + threadIdx.x;
    if (i < n) out[i] = 0.f;
}

// ---------------- gating ----------------
__global__ void gate_kernel(const float* __restrict__ X,
                            const float* __restrict__ Wg,
                            const float* __restrict__ bg)
{
    int warp = (blockIdx.x * blockDim.x + threadIdx.x) >> 5;
    int lane = threadIdx.x & 31;
    if (warp >= NT) return;
    const float* x = X + (size_t)warp * D_;
    float s[8];
    #pragma unroll
    for (int j = 0; j < 8; j++) s[j] = 0.f;
    for (int i = lane; i < D_; i += 32) {
        float xv = x[i];
        float4 w0 = *reinterpret_cast<const float4*>(Wg + (size_t)i*8);
        float4 w1 = *reinterpret_cast<const float4*>(Wg + (size_t)i*8 + 4);
        s[0] = fmaf(xv, w0.x, s[0]); s[1] = fmaf(xv, w0.y, s[1]);
        s[2] = fmaf(xv, w0.z, s[2]); s[3] = fmaf(xv, w0.w, s[3]);
        s[4] = fmaf(xv, w1.x, s[4]); s[5] = fmaf(xv, w1.y, s[5]);
        s[6] = fmaf(xv, w1.z, s[6]); s[7] = fmaf(xv, w1.w, s[7]);
    }
    #pragma unroll
    for (int off = 16; off > 0; off >>= 1)
        #pragma unroll
        for (int j = 0; j < 8; j++)
            s[j] += __shfl_xor_sync(0xffffffffu, s[j], off);
    if (lane == 0) {
        #pragma unroll
        for (int j = 0; j < 8; j++) s[j] += bg[j];
        int i1 = 0;
        #pragma unroll
        for (int j = 1; j < 8; j++) if (s[j] > s[i1]) i1 = j;
        int i2 = -1; float b2 = -1e30f;
        #pragma unroll
        for (int j = 0; j < 8; j++) if (j != i1 && s[j] > b2) { b2 = s[j]; i2 = j; }
        float a1 = 1.f / (1.f + expf(b2 - s[i1]));
        g_m1[warp] = (unsigned char)(i1 + 1);
        g_m2[warp] = (unsigned char)(i2 + 1);
        g_a1[warp] = a1;
        g_a2[warp] = 1.f - a1;
    }
}

// ---------------- pack ----------------
__global__ __launch_bounds__(256) void pack_kernel()
{
    int bm = blockIdx.x;          // 0..63
    int b  = bm >> 3;
    int m  = (bm & 7) + 1;        // 1..8
    __shared__ int wsum[8];
    int tid = threadIdx.x;
    int lane = tid & 31, w = tid >> 5;
    int base = 0;
    int segbase = (b*NM_ + m - 1) * T_;
    for (int t0 = 0; t0 < T_; t0 += 256) {
        int t = t0 + tid;
        int n = t*B_ + b;
        int sel = 0; float a = 0.f;
        int m1v = g_m1[n], m2v = g_m2[n];
        if      (m1v == m) { sel = 1; a = g_a1[n]; }
        else if (m2v == m) { sel = 1; a = g_a2[n]; }
        int incl = sel;
        #pragma unroll
        for (int off = 1; off < 32; off <<= 1) {
            int u = __shfl_up_sync(0xffffffffu, incl, off);
            if (lane >= off) incl += u;
        }
        if (lane == 31) wsum[w] = incl;
        __syncthreads();
        int woff = 0, tot = 0;
        #pragma unroll
        for (int i = 0; i < 8; i++) { int v = wsum[i]; tot += v; if (i < w) woff += v; }
        if (sel) {
            int pos = base + woff + incl - 1;
            g_tok[segbase + pos] = t;
            g_pa [segbase + pos] = a;
        }
        base += tot;
        __syncthreads();
    }
    if (tid == 0) g_cnt[b*NM_ + m - 1] = base;
}

// ---------------- packed K|V projection via tf32 mma ----------------
// Tile: 128 packed rows x (64 K cols | 64 V cols). K-dim 1024 in steps of 16.
// 8 warps = 4(M) x 2(N); warp tile 32x64; mma m16n8k8.
#define AP 132
__global__ __launch_bounds__(256, 2) void proj_kv_kernel(
    const float* __restrict__ X,
    const float* __restrict__ Wk, const float* __restrict__ bk,
    const float* __restrict__ Wv, const float* __restrict__ bv)
{
    int ci = blockIdx.x, m = blockIdx.y, b = blockIdx.z;
    int cnt = (m == 0) ? T_ : g_cnt[b*NM_ + m - 1];
    int r0 = ci << 7;
    if (r0 >= cnt) return;
    int L = cnt - r0; if (L > 128) L = 128;

    __shared__ __align__(16) unsigned As[2][16][AP];
    __shared__ __align__(16) unsigned Bs[2][16][AP];
    __shared__ int rowIdx[128];
    int tid = threadIdx.x;
    int segbase = (b*NM_ + m - 1) * T_;   // valid only for m>=1
    if (tid < 128) {
        int t = 0;
        if (tid < L) t = (m == 0) ? (r0 + tid) : g_tok[segbase + r0 + tid];
        rowIdx[tid] = t*B_ + b;
    }
    __syncthreads();

    // global-load assignments
    int aRow = tid >> 1, aHalf = tid & 1;                       // A: 128 rows x 16 cols, 8 floats/thread
    const float* aPtr = X + (size_t)rowIdx[aRow]*D_ + aHalf*8;
    int bK = tid >> 4;                                          // 0..15
    int bc = tid & 15;                                          // col block of 8: 0..15
    int bHalf = bc >> 3;                                        // 0 -> K weights, 1 -> V weights
    const float* Wsrc = bHalf ? Wv : Wk;
    const float* bPtr = Wsrc + (size_t)bK*NKV + m*HD + (bc*8 - bHalf*64);

    int lane = tid & 31, gid = lane >> 2, tig = lane & 3;
    int warpId = tid >> 5, wM = warpId & 3, wN = warpId >> 2;

    float c[2][8][4];
    #pragma unroll
    for (int mi = 0; mi < 2; mi++)
        #pragma unroll
        for (int ni = 0; ni < 8; ni++)
            #pragma unroll
            for (int j = 0; j < 4; j++) c[mi][ni][j] = 0.f;

    float4 a0r, a1r, b0r, b1r;
    // prologue: kt = 0
    a0r = *reinterpret_cast<const float4*>(aPtr);
    a1r = *reinterpret_cast<const float4*>(aPtr + 4);
    b0r = *reinterpret_cast<const float4*>(bPtr);
    b1r = *reinterpret_cast<const float4*>(bPtr + 4);
    {
        As[0][aHalf*8+0][aRow] = f2tf32(a0r.x); As[0][aHalf*8+1][aRow] = f2tf32(a0r.y);
        As[0][aHalf*8+2][aRow] = f2tf32(a0r.z); As[0][aHalf*8+3][aRow] = f2tf32(a0r.w);
        As[0][aHalf*8+4][aRow] = f2tf32(a1r.x); As[0][aHalf*8+5][aRow] = f2tf32(a1r.y);
        As[0][aHalf*8+6][aRow] = f2tf32(a1r.z); As[0][aHalf*8+7][aRow] = f2tf32(a1r.w);
        uint4 u0 = make_uint4(f2tf32(b0r.x), f2tf32(b0r.y), f2tf32(b0r.z), f2tf32(b0r.w));
        uint4 u1 = make_uint4(f2tf32(b1r.x), f2tf32(b1r.y), f2tf32(b1r.z), f2tf32(b1r.w));
        *reinterpret_cast<uint4*>(&Bs[0][bK][bc*8])     = u0;
        *reinterpret_cast<uint4*>(&Bs[0][bK][bc*8 + 4]) = u1;
    }
    __syncthreads();

    int cur = 0;
    for (int kt = 0; kt < D_; kt += 16) {
        bool more = (kt + 16 < D_);
        if (more) {
            a0r = *reinterpret_cast<const float4*>(aPtr + kt + 16);
            a1r = *reinterpret_cast<const float4*>(aPtr + kt + 20);
            b0r = *reinterpret_cast<const float4*>(bPtr + (size_t)(kt + 16)*NKV);
            b1r = *reinterpret_cast<const float4*>(bPtr + (size_t)(kt + 16)*NKV + 4);
        }
        #pragma unroll
        for (int k0 = 0; k0 < 16; k0 += 8) {
            unsigned a[2][4];
            #pragma unroll
            for (int mi = 0; mi < 2; mi++) {
                int r = wM*32 + mi*16 + gid;
                a[mi][0] = As[cur][k0 + tig    ][r];
                a[mi][1] = As[cur][k0 + tig    ][r + 8];
                a[mi][2] = As[cur][k0 + tig + 4][r];
                a[mi][3] = As[cur][k0 + tig + 4][r + 8];
            }
            #pragma unroll
            for (int ni = 0; ni < 8; ni++) {
                int cb = wN*64 + ni*8 + gid;
                unsigned b0 = Bs[cur][k0 + tig    ][cb];
                unsigned b1 = Bs[cur][k0 + tig + 4][cb];
                mma_tf32(c[0][ni], a[0][0], a[0][1], a[0][2], a[0][3], b0, b1);
                mma_tf32(c[1][ni], a[1][0], a[1][1], a[1][2], a[1][3], b0, b1);
            }
        }
        if (more) {
            int nxt = cur ^ 1;
            As[nxt][aHalf*8+0][aRow] = f2tf32(a0r.x); As[nxt][aHalf*8+1][aRow] = f2tf32(a0r.y);
            As[nxt][aHalf*8+2][aRow] = f2tf32(a0r.z); As[nxt][aHalf*8+3][aRow] = f2tf32(a0r.w);
            As[nxt][aHalf*8+4][aRow] = f2tf32(a1r.x); As[nxt][aHalf*8+5][aRow] = f2tf32(a1r.y);
            As[nxt][aHalf*8+6][aRow] = f2tf32(a1r.z); As[nxt][aHalf*8+7][aRow] = f2tf32(a1r.w);
            uint4 u0 = make_uint4(f2tf32(b0r.x), f2tf32(b0r.y), f2tf32(b0r.z), f2tf32(b0r.w));
            uint4 u1 = make_uint4(f2tf32(b1r.x), f2tf32(b1r.y), f2tf32(b1r.z), f2tf32(b1r.w));
            *reinterpret_cast<uint4*>(&Bs[nxt][bK][bc*8])     = u0;
            *reinterpret_cast<uint4*>(&Bs[nxt][bK][bc*8 + 4]) = u1;
        }
        __syncthreads();
        cur ^= 1;
    }

    // epilogue: c[mi][ni] -> (row, col) with bias; col<64 -> K, else V
    size_t segKV = ((size_t)(b*MP1 + m)*T_ + r0) * HD;
    #pragma unroll
    for (int mi = 0; mi < 2; mi++) {
        #pragma unroll
        for (int ni = 0; ni < 8; ni++) {
            int colb = wN*64 + ni*8 + tig*2;
            int half = colb >> 6;
            int cc = colb & 63;
            const float* bias = half ? bv : bk;
            float b0v = bias[m*HD + cc];
            float b1v = bias[m*HD + cc + 1];
            float* dst = (half ? g_Vp : g_Kp) + segKV + cc;
            int r1 = wM*32 + mi*16 + gid;
            if (r1 < L) {
                float2 v = make_float2(c[mi][ni][0] + b0v, c[mi][ni][1] + b1v);
                *reinterpret_cast<float2*>(dst + (size_t)r1*HD) = v;
            }
            int r2 = r1 + 8;
            if (r2 < L) {
                float2 v = make_float2(c[mi][ni][2] + b0v, c[mi][ni][3] + b1v);
                *reinterpret_cast<float2*>(dst + (size_t)r2*HD) = v;
            }
        }
    }
}

// ---------------- Q projection via tf32 mma: 64 rows x 64 cols per block ----------------
#define QP 68
__global__ __launch_bounds__(256, 2) void proj_q_kernel(
    const float* __restrict__ X,
    const float* __restrict__ Wq, const float* __restrict__ bq)
{
    __shared__ __align__(16) unsigned As[2][16][QP];
    __shared__ __align__(16) unsigned Bs[2][16][QP];
    int tid = threadIdx.x;
    int m0 = blockIdx.x * 64;

    int aRow = tid >> 2, aq = tid & 3;                       // A: 64 rows x 16 cols, 4 floats/thread
    const float* aPtr = X + (size_t)(m0 + aRow)*D_ + aq*4;
    int bK = tid >> 4, bc = tid & 15;                        // B: 16 x 64, 4 floats/thread
    const float* bPtr = Wq + (size_t)bK*HD + bc*4;

    int lane = tid & 31, gid = lane >> 2, tig = lane & 3;
    int warpId = tid >> 5, wM = warpId & 3, wN = warpId >> 2;  // 4(M) x 2(N); warp tile 16x32

    float c[4][4];
    #pragma unroll
    for (int ni = 0; ni < 4; ni++)
        #pragma unroll
        for (int j = 0; j < 4; j++) c[ni][j] = 0.f;

    float4 aR, bR;
    aR = *reinterpret_cast<const float4*>(aPtr);
    bR = *reinterpret_cast<const float4*>(bPtr);
    {
        As[0][aq*4+0][aRow] = f2tf32(aR.x); As[0][aq*4+1][aRow] = f2tf32(aR.y);
        As[0][aq*4+2][aRow] = f2tf32(aR.z); As[0][aq*4+3][aRow] = f2tf32(aR.w);
        uint4 u = make_uint4(f2tf32(bR.x), f2tf32(bR.y), f2tf32(bR.z), f2tf32(bR.w));
        *reinterpret_cast<uint4*>(&Bs[0][bK][bc*4]) = u;
    }
    __syncthreads();

    int cur = 0;
    for (int kt = 0; kt < D_; kt += 16) {
        bool more = (kt + 16 < D_);
        if (more) {
            aR = *reinterpret_cast<const float4*>(aPtr + kt + 16);
            bR = *reinterpret_cast<const float4*>(bPtr + (size_t)(kt + 16)*HD);
        }
        #pragma unroll
        for (int k0 = 0; k0 < 16; k0 += 8) {
            int r = wM*16 + gid;
            unsigned a0 = As[cur][k0 + tig    ][r];
            unsigned a1 = As[cur][k0 + tig    ][r + 8];
            unsigned a2 = As[cur][k0 + tig + 4][r];
            unsigned a3 = As[cur][k0 + tig + 4][r + 8];
            #pragma unroll
            for (int ni = 0; ni < 4; ni++) {
                int cb = wN*32 + ni*8 + gid;
                unsigned b0 = Bs[cur][k0 + tig    ][cb];
                unsigned b1 = Bs[cur][k0 + tig + 4][cb];
                mma_tf32(c[ni], a0, a1, a2, a3, b0, b1);
            }
        }
        if (more) {
            int nxt = cur ^ 1;
            As[nxt][aq*4+0][aRow] = f2tf32(aR.x); As[nxt][aq*4+1][aRow] = f2tf32(aR.y);
            As[nxt][aq*4+2][aRow] = f2tf32(aR.z); As[nxt][aq*4+3][aRow] = f2tf32(aR.w);
            uint4 u = make_uint4(f2tf32(bR.x), f2tf32(bR.y), f2tf32(bR.z), f2tf32(bR.w));
            *reinterpret_cast<uint4*>(&Bs[nxt][bK][bc*4]) = u;
        }
        __syncthreads();
        cur ^= 1;
    }

    #pragma unroll
    for (int ni = 0; ni < 4; ni++) {
        int colb = wN*32 + ni*8 + tig*2;
        float b0v = bq[colb], b1v = bq[colb + 1];
        int r1 = m0 + wM*16 + gid;
        float2 v1 = make_float2(c[ni][0] + b0v, c[ni][1] + b1v);
        *reinterpret_cast<float2*>(g_Q + (size_t)r1*HD + colb) = v1;
        float2 v2 = make_float2(c[ni][2] + b0v, c[ni][3] + b1v);
        *reinterpret_cast<float2*>(g_Q + (size_t)(r1 + 8)*HD + colb) = v2;
    }
}

// ---------------- per-chunk G = K^T V (64x64), packed contiguous rows ----------------
__global__ __launch_bounds__(256) void chunk_g_kernel()
{
    int ci = blockIdx.x, m = blockIdx.y, b = blockIdx.z;
    int cnt = (m == 0) ? T_ : g_cnt[b*NM_ + m - 1];
    if ((ci << 6) >= cnt) return;
    int L = cnt - (ci << 6); if (L > 64) L = 64;
    __shared__ float Ks[64][64];
    __shared__ float Vs[64][64];
    int tid = threadIdx.x;
    size_t segp = ((size_t)(b*MP1 + m)*T_ + (ci << 6)) * HD;
    {
        int r = tid >> 2, q4 = tid & 3;
        bool valid = r < L;
        #pragma unroll
        for (int j = 0; j < 4; j++) {
            int c = q4*16 + j*4;
            float4 kv = valid ? *reinterpret_cast<const float4*>(g_Kp + segp + (size_t)r*HD + c) : make_float4(0,0,0,0);
            float4 vv = valid ? *reinterpret_cast<const float4*>(g_Vp + segp + (size_t)r*HD + c) : make_float4(0,0,0,0);
            *reinterpret_cast<float4*>(&Ks[r][c]) = kv;
            *reinterpret_cast<float4*>(&Vs[r][c]) = vv;
        }
    }
    __syncthreads();
    int ai = tid & 15, cf = tid >> 4;
    float acc[4][4];
    #pragma unroll
    for (int i = 0; i < 4; i++)
        #pragma unroll
        for (int j = 0; j < 4; j++) acc[i][j] = 0.f;
    for (int rr = 0; rr < 64; rr++) {
        float4 ka = *reinterpret_cast<const float4*>(&Ks[rr][ai*4]);
        float4 vc = *reinterpret_cast<const float4*>(&Vs[rr][cf*4]);
        float a_[4] = {ka.x,ka.y,ka.z,ka.w};
        float v_[4] = {vc.x,vc.y,vc.z,vc.w};
        #pragma unroll
        for (int i = 0; i < 4; i++)
            #pragma unroll
            for (int j = 0; j < 4; j++)
                acc[i][j] = fmaf(a_[i], v_[j], acc[i][j]);
    }
    float* Gp = g_G + (size_t)((b*MP1 + m)*32 + ci) * 4096;
    #pragma unroll
    for (int i = 0; i < 4; i++) {
        float4 o = make_float4(acc[i][0], acc[i][1], acc[i][2], acc[i][3]);
        *reinterpret_cast<float4*>(Gp + (ai*4 + i)*64 + cf*4) = o;
    }
}

// ---------------- per-segment prefix over chunk states ----------------
__global__ __launch_bounds__(256) void prefix_kernel(const float* __restrict__ M0)
{
    int b = blockIdx.x / MP1, m = blockIdx.x % MP1;
    int cnt = (m == 0) ? T_ : g_cnt[b*NM_ + m - 1];
    int nch = (cnt + 63) >> 6;
    int tid = threadIdx.x;
    float st[16];
    #pragma unroll
    for (int k = 0; k < 16; k++) st[k] = M0[tid + 256*k];
    size_t base = (size_t)((b*MP1 + m) * 32) * 4096;
    for (int ci = 0; ci < nch; ci++) {
        size_t off = base + (size_t)ci * 4096;
        #pragma unroll
        for (int k = 0; k < 16; k++) {
            int idx = tid + 256*k;
            g_S[off + idx] = st[k];
            st[k] += g_G[off + idx];
        }
    }
}

// ---------------- per-chunk output: O = tril(Q K^T) V + Q S_c ; scatter alpha*O ----------------
__global__ __launch_bounds__(256) void chunk_o_kernel(float* __restrict__ out)
{
    int ci = blockIdx.x, m = blockIdx.y, b = blockIdx.z;
    int cnt = (m == 0) ? T_ : g_cnt[b*NM_ + m - 1];
    if ((ci << 6) >= cnt) return;
    int L = cnt - (ci << 6); if (L > 64) L = 64;

    __shared__ float Qt[64][64];   // [feat][row]
    __shared__ float KP[64][64];   // Kt [feat][tok], then Pt [tok][row]
    __shared__ float VS[64][64];   // V  [tok][feat], then S  [feat_in][feat_out]
    int tid = threadIdx.x;
    int segbase = (m == 0) ? 0 : (b*NM_ + m - 1)*T_;
    size_t segp = ((size_t)(b*MP1 + m)*T_ + (ci << 6)) * HD;
    {
        int r = tid >> 2, q4 = tid & 3;
        bool valid = r < L;
        const float* qs = g_Q;
        if (valid) {
            int i = (ci << 6) + r;
            int t = (m == 0) ? i : g_tok[segbase + i];
            qs = g_Q + ((size_t)t*B_ + b)*HD;
        }
        #pragma unroll
        for (int j = 0; j < 4; j++) {
            int c = q4*16 + j*4;
            float4 qv = valid ? *reinterpret_cast<const float4*>(qs + c) : make_float4(0,0,0,0);
            float4 kv = valid ? *reinterpret_cast<const float4*>(g_Kp + segp + (size_t)r*HD + c) : make_float4(0,0,0,0);
            float4 vv = valid ? *reinterpret_cast<const float4*>(g_Vp + segp + (size_t)r*HD + c) : make_float4(0,0,0,0);
            Qt[c+0][r] = qv.x; Qt[c+1][r] = qv.y; Qt[c+2][r] = qv.z; Qt[c+3][r] = qv.w;
            KP[c+0][r] = kv.x; KP[c+1][r] = kv.y; KP[c+2][r] = kv.z; KP[c+3][r] = kv.w;
            *reinterpret_cast<float4*>(&VS[r][c]) = vv;
        }
    }
    __syncthreads();

    int ri = tid & 15, cj = tid >> 4;
    int r0 = ri*4, c0 = cj*4;

    // stage 1: P[r][c] = q_r . k_c
    float p[4][4];
    #pragma unroll
    for (int i = 0; i < 4; i++)
        #pragma unroll
        for (int j = 0; j < 4; j++) p[i][j] = 0.f;
    for (int j = 0; j < 64; j++) {
        float4 qa = *reinterpret_cast<const float4*>(&Qt[j][r0]);
        float4 kc = *reinterpret_cast<const float4*>(&KP[j][c0]);
        float q_[4] = {qa.x,qa.y,qa.z,qa.w};
        float k_[4] = {kc.x,kc.y,kc.z,kc.w};
        #pragma unroll
        for (int i = 0; i < 4; i++)
            #pragma unroll
            for (int jj = 0; jj < 4; jj++)
                p[i][jj] = fmaf(q_[i], k_[jj], p[i][jj]);
    }
    __syncthreads();
    #pragma unroll
    for (int i = 0; i < 4; i++)
        #pragma unroll
        for (int jj = 0; jj < 4; jj++)
            KP[c0+jj][r0+i] = (c0+jj <= r0+i) ? p[i][jj] : 0.f;
    __syncthreads();

    // stage 2a: O = P V
    float o[4][4];
    #pragma unroll
    for (int i = 0; i < 4; i++)
        #pragma unroll
        for (int j = 0; j < 4; j++) o[i][j] = 0.f;
    for (int j = 0; j < 64; j++) {
        float4 pa = *reinterpret_cast<const float4*>(&KP[j][r0]);
        float4 vc = *reinterpret_cast<const float4*>(&VS[j][c0]);
        float p_[4] = {pa.x,pa.y,pa.z,pa.w};
        float v_[4] = {vc.x,vc.y,vc.z,vc.w};
        #pragma unroll
        for (int i = 0; i < 4; i++)
            #pragma unroll
            for (int jj = 0; jj < 4; jj++)
                o[i][jj] = fmaf(p_[i], v_[jj], o[i][jj]);
    }
    __syncthreads();
    {
        int r = tid >> 2, q4 = tid & 3;
        const float* Sp = g_S + (size_t)((b*MP1 + m)*32 + ci) * 4096;
        #pragma unroll
        for (int j = 0; j < 4; j++) {
            int c = q4*16 + j*4;
            *reinterpret_cast<float4*>(&VS[r][c]) = *reinterpret_cast<const float4*>(Sp + r*64 + c);
        }
    }
    __syncthreads();
    // stage 2b: O += Q S
    for (int j = 0; j < 64; j++) {
        float4 qa = *reinterpret_cast<const float4*>(&Qt[j][r0]);
        float4 sc = *reinterpret_cast<const float4*>(&VS[j][c0]);
        float q_[4] = {qa.x,qa.y,qa.z,qa.w};
        float s_[4] = {sc.x,sc.y,sc.z,sc.w};
        #pragma unroll
        for (int i = 0; i < 4; i++)
            #pragma unroll
            for (int jj = 0; jj < 4; jj++)
                o[i][jj] = fmaf(q_[i], s_[jj], o[i][jj]);
    }

    // epilogue: out[t,b,:] += alpha * O[r,:]
    #pragma unroll
    for (int i = 0; i < 4; i++) {
        int r = r0 + i;
        if (r >= L) continue;
        int idx = (ci << 6) + r;
        int t; float alpha;
        if (m == 0) { t = idx; alpha = 1.f; }
        else        { t = g_tok[segbase + idx]; alpha = g_pa[segbase + idx]; }
        float* op = out + ((size_t)t*B_ + b)*HD + c0;
        atomicAdd(op + 0, alpha * o[i][0]);
        atomicAdd(op + 1, alpha * o[i][1]);
        atomicAdd(op + 2, alpha * o[i][2]);
        atomicAdd(op + 3, alpha * o[i][3]);
    }
}

// ---------------- launch ----------------
extern "C" void kernel_launch(void* const* d_in, const int* in_sizes, int n_in,
                              void* d_out, int out_size)
{
    const float* X  = (const float*)d_in[0];
    const float* M0 = (const float*)d_in[1];
    const float* Wq = (const float*)d_in[2];
    const float* bq = (const float*)d_in[3];
    const float* Wk = (const float*)d_in[4];
    const float* bk = (const float*)d_in[5];
    const float* Wv = (const float*)d_in[6];
    const float* bv = (const float*)d_in[7];
    const float* Wg = (const float*)d_in[8];
    const float* bg = (const float*)d_in[9];
    float* out = (float*)d_out;

    zero_kernel<<<(NT*HD + 255)/256, 256>>>(out, NT*HD);
    gate_kernel<<<NT/8, 256>>>(X, Wg, bg);
    pack_kernel<<<64, 256>>>();

    proj_q_kernel<<<NT/64, 256>>>(X, Wq, bq);
    proj_kv_kernel<<<dim3(16, MP1, B_), 256>>>(X, Wk, bk, Wv, bv);

    chunk_g_kernel<<<dim3(32, MP1, B_), 256>>>();
    prefix_kernel<<<B_*MP1, 256>>>(M0);
    chunk_o_kernel<<<dim3(32, MP1, B_), 256>>>(out);
}

// round 7
// speedup vs baseline: 4.5436x; 1.1559x over previous
#include <cuda_runtime.h>
#include <math.h>

#define T_   2048
#define B_   8
#define D_   1024
#define HD   64      // d
#define NM_  8
#define MP1  9
#define NT   (T_*B_)     // 16384 tokens
#define NKV  576         // Mp1 * d

// ---------------- static device scratch ----------------
__device__ float g_Q[NT*HD];                                // 4 MB  (row-major [token, d]; token = t*B+b)
__device__ float g_Kp[(size_t)B_*MP1*T_*HD];                // packed K per (b,m): 36 MB
__device__ float g_Vp[(size_t)B_*MP1*T_*HD];                // packed V per (b,m): 36 MB
#define NSLOT (B_*MP1*32)                                   // 2304 chunk slots
__device__ float g_G[(size_t)NSLOT*HD*HD];                  // per-chunk K^T V
__device__ float g_S[(size_t)NSLOT*HD*HD];                  // per-chunk starting state
__device__ int   g_tok[B_*NM_*T_];                          // packed token time per (b,m>=1)
__device__ float g_pa [B_*NM_*T_];                          // packed alpha per (b,m>=1)
__device__ int   g_cnt[B_*NM_];                             // segment lengths
__device__ unsigned char g_m1[NT], g_m2[NT];
__device__ float g_a1[NT], g_a2[NT];
// tf32-preconverted operands
__device__ unsigned g_Xt[(size_t)NT*D_];                    // 64 MB
__device__ unsigned g_Wqt[D_*HD];
__device__ unsigned g_Wkt[D_*NKV];
__device__ unsigned g_Wvt[D_*NKV];

// ---------------- tf32 mma helpers ----------------
__device__ __forceinline__ unsigned f2tf32(float f) {
    unsigned u;
    asm("cvt.rna.tf32.f32 %0, %1;" : "=r"(u) : "f"(f));
    return u;
}
__device__ __forceinline__ void mma_tf32(float* c,
    unsigned a0, unsigned a1, unsigned a2, unsigned a3,
    unsigned b0, unsigned b1)
{
    asm volatile(
        "mma.sync.aligned.m16n8k8.row.col.f32.tf32.tf32.f32 "
        "{%0,%1,%2,%3}, {%4,%5,%6,%7}, {%8,%9}, {%0,%1,%2,%3};"
        : "+f"(c[0]), "+f"(c[1]), "+f"(c[2]), "+f"(c[3])
        : "r"(a0), "r"(a1), "r"(a2), "r"(a3), "r"(b0), "r"(b1));
}
__device__ __forceinline__ void cp16(void* dst, const void* src) {
    unsigned s = (unsigned)__cvta_generic_to_shared(dst);
    asm volatile("cp.async.cg.shared.global [%0], [%1], 16;" :: "r"(s), "l"(src));
}
#define CP_COMMIT() asm volatile("cp.async.commit_group;" ::)
#define CP_WAIT1()  asm volatile("cp.async.wait_group 1;" ::)

// ---------------- zero output ----------------
__global__ void zero_kernel(float* __restrict__ out, int n)
{
    int i = blockIdx.x * blockDim.x + threadIdx.x;
    if (i < n) out[i] = 0.f;
}

// ---------------- weight tf32 conversion ----------------
__global__ void wconvert_kernel(const float* __restrict__ Wq,
                                const float* __restrict__ Wk,
                                const float* __restrict__ Wv)
{
    int i = blockIdx.x * blockDim.x + threadIdx.x;
    if (i < D_*HD) g_Wqt[i] = f2tf32(Wq[i]);
    if (i < D_*NKV) {
        g_Wkt[i] = f2tf32(Wk[i]);
        g_Wvt[i] = f2tf32(Wv[i]);
    }
}

// ---------------- gating (also emits tf32 X) ----------------
__global__ void gate_kernel(const float* __restrict__ X,
                            const float* __restrict__ Wg,
                            const float* __restrict__ bg)
{
    int warp = (blockIdx.x * blockDim.x + threadIdx.x) >> 5;
    int lane = threadIdx.x & 31;
    if (warp >= NT) return;
    const float* x = X + (size_t)warp * D_;
    float s[8];
    #pragma unroll
    for (int j = 0; j < 8; j++) s[j] = 0.f;
    for (int i = lane; i < D_; i += 32) {
        float xv = x[i];
        g_Xt[(size_t)warp*D_ + i] = f2tf32(xv);
        float4 w0 = *reinterpret_cast<const float4*>(Wg + (size_t)i*8);
        float4 w1 = *reinterpret_cast<const float4*>(Wg + (size_t)i*8 + 4);
        s[0] = fmaf(xv, w0.x, s[0]); s[1] = fmaf(xv, w0.y, s[1]);
        s[2] = fmaf(xv, w0.z, s[2]); s[3] = fmaf(xv, w0.w, s[3]);
        s[4] = fmaf(xv, w1.x, s[4]); s[5] = fmaf(xv, w1.y, s[5]);
        s[6] = fmaf(xv, w1.z, s[6]); s[7] = fmaf(xv, w1.w, s[7]);
    }
    #pragma unroll
    for (int off = 16; off > 0; off >>= 1)
        #pragma unroll
        for (int j = 0; j < 8; j++)
            s[j] += __shfl_xor_sync(0xffffffffu, s[j], off);
    if (lane == 0) {
        #pragma unroll
        for (int j = 0; j < 8; j++) s[j] += bg[j];
        int i1 = 0;
        #pragma unroll
        for (int j = 1; j < 8; j++) if (s[j] > s[i1]) i1 = j;
        int i2 = -1; float b2 = -1e30f;
        #pragma unroll
        for (int j = 0; j < 8; j++) if (j != i1 && s[j] > b2) { b2 = s[j]; i2 = j; }
        float a1 = 1.f / (1.f + expf(b2 - s[i1]));
        g_m1[warp] = (unsigned char)(i1 + 1);
        g_m2[warp] = (unsigned char)(i2 + 1);
        g_a1[warp] = a1;
        g_a2[warp] = 1.f - a1;
    }
}

// ---------------- pack ----------------
__global__ __launch_bounds__(256) void pack_kernel()
{
    int bm = blockIdx.x;          // 0..63
    int b  = bm >> 3;
    int m  = (bm & 7) + 1;        // 1..8
    __shared__ int wsum[8];
    int tid = threadIdx.x;
    int lane = tid & 31, w = tid >> 5;
    int base = 0;
    int segbase = (b*NM_ + m - 1) * T_;
    for (int t0 = 0; t0 < T_; t0 += 256) {
        int t = t0 + tid;
        int n = t*B_ + b;
        int sel = 0; float a = 0.f;
        int m1v = g_m1[n], m2v = g_m2[n];
        if      (m1v == m) { sel = 1; a = g_a1[n]; }
        else if (m2v == m) { sel = 1; a = g_a2[n]; }
        int incl = sel;
        #pragma unroll
        for (int off = 1; off < 32; off <<= 1) {
            int u = __shfl_up_sync(0xffffffffu, incl, off);
            if (lane >= off) incl += u;
        }
        if (lane == 31) wsum[w] = incl;
        __syncthreads();
        int woff = 0, tot = 0;
        #pragma unroll
        for (int i = 0; i < 8; i++) { int v = wsum[i]; tot += v; if (i < w) woff += v; }
        if (sel) {
            int pos = base + woff + incl - 1;
            g_tok[segbase + pos] = t;
            g_pa [segbase + pos] = a;
        }
        base += tot;
        __syncthreads();
    }
    if (tid == 0) g_cnt[b*NM_ + m - 1] = base;
}

// ---------------- packed K|V projection: tf32 mma + cp.async 3-stage ----------------
// Tile: 128 packed rows x (64 K | 64 V). K-step 16, 64 iters.
// 8 warps = 4(M) x 2(N); warp tile 32x64; mma m16n8k8.
#define KV_AP 20
#define KV_BP 136
#define KV_SMEM ((3*128*KV_AP + 3*16*KV_BP + 128) * 4)
__global__ __launch_bounds__(256, 2) void proj_kv_kernel(
    const float* __restrict__ bk, const float* __restrict__ bv)
{
    int ci = blockIdx.x, m = blockIdx.y, b = blockIdx.z;
    int cnt = (m == 0) ? T_ : g_cnt[b*NM_ + m - 1];
    int r0 = ci << 7;
    if (r0 >= cnt) return;
    int L = cnt - r0; if (L > 128) L = 128;

    extern __shared__ __align__(16) unsigned smem[];
    unsigned (*As)[128][KV_AP] = reinterpret_cast<unsigned(*)[128][KV_AP]>(smem);
    unsigned (*Bs)[16][KV_BP]  = reinterpret_cast<unsigned(*)[16][KV_BP]>(smem + 3*128*KV_AP);
    int* rowIdx = reinterpret_cast<int*>(smem + 3*128*KV_AP + 3*16*KV_BP);

    int tid = threadIdx.x;
    int segbase = (b*NM_ + m - 1) * T_;   // valid only for m>=1
    if (tid < 128) {
        int t = 0;
        if (tid < L) t = (m == 0) ? (r0 + tid) : g_tok[segbase + r0 + tid];
        rowIdx[tid] = t*B_ + b;
    }
    __syncthreads();

    // cp.async thread mapping (4 chunks of 16B per thread per stage)
    int aRow = tid >> 1, aOff = (tid & 1) * 8;          // A: 128 rows x 16 cols
    int bK   = tid >> 4;                                // 0..15
    int bj   = (tid & 15) * 8;                          // 0..120 (col within 128)
    int bHalf = bj >> 6;                                // 0 -> K weights, 1 -> V weights
    int bo    = bj & 63;
    const unsigned* Wt = bHalf ? g_Wvt : g_Wkt;
    const unsigned* aBase = g_Xt + (size_t)rowIdx[aRow]*D_ + aOff;
    const unsigned* bBase = Wt + (size_t)bK*NKV + m*HD + bo;

    auto issue = [&](int s, int kt) {
        const unsigned* asrc = aBase + kt;
        cp16(&As[s][aRow][aOff],     asrc);
        cp16(&As[s][aRow][aOff + 4], asrc + 4);
        const unsigned* bsrc = bBase + (size_t)kt*NKV;
        cp16(&Bs[s][bK][bj],     bsrc);
        cp16(&Bs[s][bK][bj + 4], bsrc + 4);
    };

    int lane = tid & 31, gid = lane >> 2, tig = lane & 3;
    int warpId = tid >> 5, wM = warpId & 3, wN = warpId >> 2;

    float c[2][8][4];
    #pragma unroll
    for (int mi = 0; mi < 2; mi++)
        #pragma unroll
        for (int ni = 0; ni < 8; ni++)
            #pragma unroll
            for (int j = 0; j < 4; j++) c[mi][ni][j] = 0.f;

    issue(0, 0);  CP_COMMIT();
    issue(1, 16); CP_COMMIT();

    for (int it = 0; it < 64; it++) {
        CP_WAIT1();
        __syncthreads();
        if (it + 2 < 64) issue((it + 2) % 3, (it + 2) * 16);
        CP_COMMIT();
        int s = it % 3;
        #pragma unroll
        for (int k0 = 0; k0 < 16; k0 += 8) {
            unsigned a[2][4];
            #pragma unroll
            for (int mi = 0; mi < 2; mi++) {
                int r = wM*32 + mi*16 + gid;
                a[mi][0] = As[s][r    ][k0 + tig];
                a[mi][1] = As[s][r + 8][k0 + tig];
                a[mi][2] = As[s][r    ][k0 + tig + 4];
                a[mi][3] = As[s][r + 8][k0 + tig + 4];
            }
            #pragma unroll
            for (int ni = 0; ni < 8; ni++) {
                int cb = wN*64 + ni*8 + gid;
                unsigned b0 = Bs[s][k0 + tig    ][cb];
                unsigned b1 = Bs[s][k0 + tig + 4][cb];
                mma_tf32(c[0][ni], a[0][0], a[0][1], a[0][2], a[0][3], b0, b1);
                mma_tf32(c[1][ni], a[1][0], a[1][1], a[1][2], a[1][3], b0, b1);
            }
        }
    }

    // epilogue: c[mi][ni] -> (row, col) with bias; col<64 -> K, else V
    size_t segKV = ((size_t)(b*MP1 + m)*T_ + r0) * HD;
    #pragma unroll
    for (int mi = 0; mi < 2; mi++) {
        #pragma unroll
        for (int ni = 0; ni < 8; ni++) {
            int colb = wN*64 + ni*8 + tig*2;
            int half = colb >> 6;
            int cc = colb & 63;
            const float* bias = half ? bv : bk;
            float b0v = bias[m*HD + cc];
            float b1v = bias[m*HD + cc + 1];
            float* dst = (half ? g_Vp : g_Kp) + segKV + cc;
            int r1 = wM*32 + mi*16 + gid;
            if (r1 < L) {
                float2 v = make_float2(c[mi][ni][0] + b0v, c[mi][ni][1] + b1v);
                *reinterpret_cast<float2*>(dst + (size_t)r1*HD) = v;
            }
            int r2 = r1 + 8;
            if (r2 < L) {
                float2 v = make_float2(c[mi][ni][2] + b0v, c[mi][ni][3] + b1v);
                *reinterpret_cast<float2*>(dst + (size_t)r2*HD) = v;
            }
        }
    }
}

// ---------------- Q projection: tf32 mma + cp.async 3-stage, 64x64 tile ----------------
#define Q_AP 20
#define Q_BP 72
__global__ __launch_bounds__(256, 2) void proj_q_kernel(
    const float* __restrict__ bq)
{
    __shared__ __align__(16) unsigned As[3][64][Q_AP];
    __shared__ __align__(16) unsigned Bs[3][16][Q_BP];
    int tid = threadIdx.x;
    int m0 = blockIdx.x * 64;

    // cp.async mapping: A 256 chunks (tid<128, 2 each), B 256 chunks (tid>=128, 2 each)
    int aRow = (tid & 127) >> 1, aOff = (tid & 1) * 8;
    int t2 = tid & 127;
    int bK = t2 >> 3, bj = (t2 & 7) * 8;
    const unsigned* aBase = g_Xt + (size_t)(m0 + aRow)*D_ + aOff;
    const unsigned* bBase = g_Wqt + (size_t)bK*HD + bj;
    bool isA = (tid < 128);

    auto issue = [&](int s, int kt) {
        if (isA) {
            const unsigned* asrc = aBase + kt;
            cp16(&As[s][aRow][aOff],     asrc);
            cp16(&As[s][aRow][aOff + 4], asrc + 4);
        } else {
            const unsigned* bsrc = bBase + (size_t)kt*HD;
            cp16(&Bs[s][bK][bj],     bsrc);
            cp16(&Bs[s][bK][bj + 4], bsrc + 4);
        }
    };

    int lane = tid & 31, gid = lane >> 2, tig = lane & 3;
    int warpId = tid >> 5, wM = warpId & 3, wN = warpId >> 2;  // 4(M) x 2(N); warp tile 16x32

    float c[4][4];
    #pragma unroll
    for (int ni = 0; ni < 4; ni++)
        #pragma unroll
        for (int j = 0; j < 4; j++) c[ni][j] = 0.f;

    issue(0, 0);  CP_COMMIT();
    issue(1, 16); CP_COMMIT();

    for (int it = 0; it < 64; it++) {
        CP_WAIT1();
        __syncthreads();
        if (it + 2 < 64) issue((it + 2) % 3, (it + 2) * 16);
        CP_COMMIT();
        int s = it % 3;
        #pragma unroll
        for (int k0 = 0; k0 < 16; k0 += 8) {
            int r = wM*16 + gid;
            unsigned a0 = As[s][r    ][k0 + tig];
            unsigned a1 = As[s][r + 8][k0 + tig];
            unsigned a2 = As[s][r    ][k0 + tig + 4];
            unsigned a3 = As[s][r + 8][k0 + tig + 4];
            #pragma unroll
            for (int ni = 0; ni < 4; ni++) {
                int cb = wN*32 + ni*8 + gid;
                unsigned b0 = Bs[s][k0 + tig    ][cb];
                unsigned b1 = Bs[s][k0 + tig + 4][cb];
                mma_tf32(c[ni], a0, a1, a2, a3, b0, b1);
            }
        }
    }

    #pragma unroll
    for (int ni = 0; ni < 4; ni++) {
        int colb = wN*32 + ni*8 + tig*2;
        float b0v = bq[colb], b1v = bq[colb + 1];
        int r1 = m0 + wM*16 + gid;
        float2 v1 = make_float2(c[ni][0] + b0v, c[ni][1] + b1v);
        *reinterpret_cast<float2*>(g_Q + (size_t)r1*HD + colb) = v1;
        float2 v2 = make_float2(c[ni][2] + b0v, c[ni][3] + b1v);
        *reinterpret_cast<float2*>(g_Q + (size_t)(r1 + 8)*HD + colb) = v2;
    }
}

// ---------------- per-chunk G = K^T V (64x64), packed contiguous rows ----------------
__global__ __launch_bounds__(256) void chunk_g_kernel()
{
    int ci = blockIdx.x, m = blockIdx.y, b = blockIdx.z;
    int cnt = (m == 0) ? T_ : g_cnt[b*NM_ + m - 1];
    if ((ci << 6) >= cnt) return;
    int L = cnt - (ci << 6); if (L > 64) L = 64;
    __shared__ float Ks[64][64];
    __shared__ float Vs[64][64];
    int tid = threadIdx.x;
    size_t segp = ((size_t)(b*MP1 + m)*T_ + (ci << 6)) * HD;
    {
        int r = tid >> 2, q4 = tid & 3;
        bool valid = r < L;
        #pragma unroll
        for (int j = 0; j < 4; j++) {
            int c = q4*16 + j*4;
            float4 kv = valid ? *reinterpret_cast<const float4*>(g_Kp + segp + (size_t)r*HD + c) : make_float4(0,0,0,0);
            float4 vv = valid ? *reinterpret_cast<const float4*>(g_Vp + segp + (size_t)r*HD + c) : make_float4(0,0,0,0);
            *reinterpret_cast<float4*>(&Ks[r][c]) = kv;
            *reinterpret_cast<float4*>(&Vs[r][c]) = vv;
        }
    }
    __syncthreads();
    int ai = tid & 15, cf = tid >> 4;
    float acc[4][4];
    #pragma unroll
    for (int i = 0; i < 4; i++)
        #pragma unroll
        for (int j = 0; j < 4; j++) acc[i][j] = 0.f;
    for (int rr = 0; rr < 64; rr++) {
        float4 ka = *reinterpret_cast<const float4*>(&Ks[rr][ai*4]);
        float4 vc = *reinterpret_cast<const float4*>(&Vs[rr][cf*4]);
        float a_[4] = {ka.x,ka.y,ka.z,ka.w};
        float v_[4] = {vc.x,vc.y,vc.z,vc.w};
        #pragma unroll
        for (int i = 0; i < 4; i++)
            #pragma unroll
            for (int j = 0; j < 4; j++)
                acc[i][j] = fmaf(a_[i], v_[j], acc[i][j]);
    }
    float* Gp = g_G + (size_t)((b*MP1 + m)*32 + ci) * 4096;
    #pragma unroll
    for (int i = 0; i < 4; i++) {
        float4 o = make_float4(acc[i][0], acc[i][1], acc[i][2], acc[i][3]);
        *reinterpret_cast<float4*>(Gp + (ai*4 + i)*64 + cf*4) = o;
    }
}

// ---------------- per-segment prefix over chunk states ----------------
__global__ __launch_bounds__(256) void prefix_kernel(const float* __restrict__ M0)
{
    int b = blockIdx.x / MP1, m = blockIdx.x % MP1;
    int cnt = (m == 0) ? T_ : g_cnt[b*NM_ + m - 1];
    int nch = (cnt + 63) >> 6;
    int tid = threadIdx.x;
    float st[16];
    #pragma unroll
    for (int k = 0; k < 16; k++) st[k] = M0[tid + 256*k];
    size_t base = (size_t)((b*MP1 + m) * 32) * 4096;
    for (int ci = 0; ci < nch; ci++) {
        size_t off = base + (size_t)ci * 4096;
        #pragma unroll
        for (int k = 0; k < 16; k++) {
            int idx = tid + 256*k;
            g_S[off + idx] = st[k];
            st[k] += g_G[off + idx];
        }
    }
}

// ---------------- per-chunk output: O = tril(Q K^T) V + Q S_c ; scatter alpha*O ----------------
__global__ __launch_bounds__(256) void chunk_o_kernel(float* __restrict__ out)
{
    int ci = blockIdx.x, m = blockIdx.y, b = blockIdx.z;
    int cnt = (m == 0) ? T_ : g_cnt[b*NM_ + m - 1];
    if ((ci << 6) >= cnt) return;
    int L = cnt - (ci << 6); if (L > 64) L = 64;

    __shared__ float Qt[64][64];   // [feat][row]
    __shared__ float KP[64][64];   // Kt [feat][tok], then Pt [tok][row]
    __shared__ float VS[64][64];   // V  [tok][feat], then S  [feat_in][feat_out]
    int tid = threadIdx.x;
    int segbase = (m == 0) ? 0 : (b*NM_ + m - 1)*T_;
    size_t segp = ((size_t)(b*MP1 + m)*T_ + (ci << 6)) * HD;
    {
        int r = tid >> 2, q4 = tid & 3;
        bool valid = r < L;
        const float* qs = g_Q;
        if (valid) {
            int i = (ci << 6) + r;
            int t = (m == 0) ? i : g_tok[segbase + i];
            qs = g_Q + ((size_t)t*B_ + b)*HD;
        }
        #pragma unroll
        for (int j = 0; j < 4; j++) {
            int c = q4*16 + j*4;
            float4 qv = valid ? *reinterpret_cast<const float4*>(qs + c) : make_float4(0,0,0,0);
            float4 kv = valid ? *reinterpret_cast<const float4*>(g_Kp + segp + (size_t)r*HD + c) : make_float4(0,0,0,0);
            float4 vv = valid ? *reinterpret_cast<const float4*>(g_Vp + segp + (size_t)r*HD + c) : make_float4(0,0,0,0);
            Qt[c+0][r] = qv.x; Qt[c+1][r] = qv.y; Qt[c+2][r] = qv.z; Qt[c+3][r] = qv.w;
            KP[c+0][r] = kv.x; KP[c+1][r] = kv.y; KP[c+2][r] = kv.z; KP[c+3][r] = kv.w;
            *reinterpret_cast<float4*>(&VS[r][c]) = vv;
        }
    }
    __syncthreads();

    int ri = tid & 15, cj = tid >> 4;
    int r0 = ri*4, c0 = cj*4;

    // stage 1: P[r][c] = q_r . k_c
    float p[4][4];
    #pragma unroll
    for (int i = 0; i < 4; i++)
        #pragma unroll
        for (int j = 0; j < 4; j++) p[i][j] = 0.f;
    for (int j = 0; j < 64; j++) {
        float4 qa = *reinterpret_cast<const float4*>(&Qt[j][r0]);
        float4 kc = *reinterpret_cast<const float4*>(&KP[j][c0]);
        float q_[4] = {qa.x,qa.y,qa.z,qa.w};
        float k_[4] = {kc.x,kc.y,kc.z,kc.w};
        #pragma unroll
        for (int i = 0; i < 4; i++)
            #pragma unroll
            for (int jj = 0; jj < 4; jj++)
                p[i][jj] = fmaf(q_[i], k_[jj], p[i][jj]);
    }
    __syncthreads();
    #pragma unroll
    for (int i = 0; i < 4; i++)
        #pragma unroll
        for (int jj = 0; jj < 4; jj++)
            KP[c0+jj][r0+i] = (c0+jj <= r0+i) ? p[i][jj] : 0.f;
    __syncthreads();

    // stage 2a: O = P V
    float o[4][4];
    #pragma unroll
    for (int i = 0; i < 4; i++)
        #pragma unroll
        for (int j = 0; j < 4; j++) o[i][j] = 0.f;
    for (int j = 0; j < 64; j++) {
        float4 pa = *reinterpret_cast<const float4*>(&KP[j][r0]);
        float4 vc = *reinterpret_cast<const float4*>(&VS[j][c0]);
        float p_[4] = {pa.x,pa.y,pa.z,pa.w};
        float v_[4] = {vc.x,vc.y,vc.z,vc.w};
        #pragma unroll
        for (int i = 0; i < 4; i++)
            #pragma unroll
            for (int jj = 0; jj < 4; jj++)
                o[i][jj] = fmaf(p_[i], v_[jj], o[i][jj]);
    }
    __syncthreads();
    {
        int r = tid >> 2, q4 = tid & 3;
        const float* Sp = g_S + (size_t)((b*MP1 + m)*32 + ci) * 4096;
        #pragma unroll
        for (int j = 0; j < 4; j++) {
            int c = q4*16 + j*4;
            *reinterpret_cast<float4*>(&VS[r][c]) = *reinterpret_cast<const float4*>(Sp + r*64 + c);
        }
    }
    __syncthreads();
    // stage 2b: O += Q S
    for (int j = 0; j < 64; j++) {
        float4 qa = *reinterpret_cast<const float4*>(&Qt[j][r0]);
        float4 sc = *reinterpret_cast<const float4*>(&VS[j][c0]);
        float q_[4] = {qa.x,qa.y,qa.z,qa.w};
        float s_[4] = {sc.x,sc.y,sc.z,sc.w};
        #pragma unroll
        for (int i = 0; i < 4; i++)
            #pragma unroll
            for (int jj = 0; jj < 4; jj++)
                o[i][jj] = fmaf(q_[i], s_[jj], o[i][jj]);
    }

    // epilogue: out[t,b,:] += alpha * O[r,:]
    #pragma unroll
    for (int i = 0; i < 4; i++) {
        int r = r0 + i;
        if (r >= L) continue;
        int idx = (ci << 6) + r;
        int t; float alpha;
        if (m == 0) { t = idx; alpha = 1.f; }
        else        { t = g_tok[segbase + idx]; alpha = g_pa[segbase + idx]; }
        float* op = out + ((size_t)t*B_ + b)*HD + c0;
        atomicAdd(op + 0, alpha * o[i][0]);
        atomicAdd(op + 1, alpha * o[i][1]);
        atomicAdd(op + 2, alpha * o[i][2]);
        atomicAdd(op + 3, alpha * o[i][3]);
    }
}

// ---------------- launch ----------------
extern "C" void kernel_launch(void* const* d_in, const int* in_sizes, int n_in,
                              void* d_out, int out_size)
{
    const float* X  = (const float*)d_in[0];
    const float* M0 = (const float*)d_in[1];
    const float* Wq = (const float*)d_in[2];
    const float* bq = (const float*)d_in[3];
    const float* Wk = (const float*)d_in[4];
    const float* bk = (const float*)d_in[5];
    const float* Wv = (const float*)d_in[6];
    const float* bv = (const float*)d_in[7];
    const float* Wg = (const float*)d_in[8];
    const float* bg = (const float*)d_in[9];
    float* out = (float*)d_out;

    cudaFuncSetAttribute(proj_kv_kernel,
                         cudaFuncAttributeMaxDynamicSharedMemorySize, KV_SMEM);

    zero_kernel<<<(NT*HD + 255)/256, 256>>>(out, NT*HD);
    gate_kernel<<<NT/8, 256>>>(X, Wg, bg);
    wconvert_kernel<<<(D_*NKV + 255)/256, 256>>>(Wq, Wk, Wv);
    pack_kernel<<<64, 256>>>();

    proj_q_kernel<<<NT/64, 256>>>(bq);
    proj_kv_kernel<<<dim3(16, MP1, B_), 256, KV_SMEM>>>(bk, bv);

    chunk_g_kernel<<<dim3(32, MP1, B_), 256>>>();
    prefix_kernel<<<B_*MP1, 256>>>(M0);
    chunk_o_kernel<<<dim3(32, MP1, B_), 256>>>(out);
}

// round 8
// speedup vs baseline: 5.3291x; 1.1729x over previous
#include <cuda_runtime.h>
#include <math.h>

#define T_   2048
#define B_   8
#define D_   1024
#define HD   64      // d
#define NM_  8
#define MP1  9
#define NT   (T_*B_)     // 16384 tokens
#define NKV  576         // Mp1 * d

// ---------------- static device scratch ----------------
__device__ float g_Q[NT*HD];                                // tf32-valued fp32
__device__ float g_Kp[(size_t)B_*MP1*T_*HD];                // packed K per (b,m), tf32-valued
__device__ float g_Vp[(size_t)B_*MP1*T_*HD];                // packed V per (b,m), tf32-valued
#define NSLOT (B_*MP1*32)
__device__ float g_G[(size_t)NSLOT*HD*HD];                  // per-chunk K^T V (fp32)
__device__ float g_S[(size_t)NSLOT*HD*HD];                  // chunk start state (tf32-valued)
__device__ int   g_tok[B_*NM_*T_];
__device__ float g_pa [B_*NM_*T_];
__device__ int   g_cnt[B_*NM_];
__device__ unsigned char g_m1[NT], g_m2[NT];
__device__ float g_a1[NT], g_a2[NT];
__device__ unsigned g_Xt[(size_t)NT*D_];                    // X in tf32 bits
__device__ unsigned g_Wqt[D_*HD];
__device__ unsigned g_Wkt[D_*NKV];
__device__ unsigned g_Wvt[D_*NKV];

// ---------------- tf32 mma helpers ----------------
__device__ __forceinline__ unsigned f2tf32(float f) {
    unsigned u;
    asm("cvt.rna.tf32.f32 %0, %1;" : "=r"(u) : "f"(f));
    return u;
}
__device__ __forceinline__ float f2tf32f(float f) { return __uint_as_float(f2tf32(f)); }
__device__ __forceinline__ void mma_tf32(float* c,
    unsigned a0, unsigned a1, unsigned a2, unsigned a3,
    unsigned b0, unsigned b1)
{
    asm volatile(
        "mma.sync.aligned.m16n8k8.row.col.f32.tf32.tf32.f32 "
        "{%0,%1,%2,%3}, {%4,%5,%6,%7}, {%8,%9}, {%0,%1,%2,%3};"
        : "+f"(c[0]), "+f"(c[1]), "+f"(c[2]), "+f"(c[3])
        : "r"(a0), "r"(a1), "r"(a2), "r"(a3), "r"(b0), "r"(b1));
}
__device__ __forceinline__ void cp16(void* dst, const void* src) {
    unsigned s = (unsigned)__cvta_generic_to_shared(dst);
    asm volatile("cp.async.cg.shared.global [%0], [%1], 16;" :: "r"(s), "l"(src));
}
#define CP_COMMIT() asm volatile("cp.async.commit_group;" ::)
#define CP_WAIT1()  asm volatile("cp.async.wait_group 1;" ::)

// ---------------- fused prep: gate (+tf32 X) | zero out | weight convert ----------------
#define GATE_BLKS 2048
#define ZERO_BLKS 1024
#define WCONV_BLKS 2304
__global__ __launch_bounds__(256) void prep_kernel(
    const float* __restrict__ X, const float* __restrict__ Wg, const float* __restrict__ bg,
    const float* __restrict__ Wq, const float* __restrict__ Wk, const float* __restrict__ Wv,
    float* __restrict__ out)
{
    int bx = blockIdx.x;
    if (bx >= GATE_BLKS) {
        if (bx < GATE_BLKS + ZERO_BLKS) {
            int i = (bx - GATE_BLKS) * 256 + threadIdx.x;
            reinterpret_cast<float4*>(out)[i] = make_float4(0.f, 0.f, 0.f, 0.f);
        } else {
            int i = (bx - GATE_BLKS - ZERO_BLKS) * 256 + threadIdx.x;
            if (i < D_*HD) g_Wqt[i] = f2tf32(Wq[i]);
            g_Wkt[i] = f2tf32(Wk[i]);
            g_Wvt[i] = f2tf32(Wv[i]);
        }
        return;
    }
    int warp = (bx * 256 + threadIdx.x) >> 5;
    int lane = threadIdx.x & 31;
    const float* x = X + (size_t)warp * D_;
    float s[8];
    #pragma unroll
    for (int j = 0; j < 8; j++) s[j] = 0.f;
    for (int i = lane; i < D_; i += 32) {
        float xv = x[i];
        g_Xt[(size_t)warp*D_ + i] = f2tf32(xv);
        float4 w0 = *reinterpret_cast<const float4*>(Wg + (size_t)i*8);
        float4 w1 = *reinterpret_cast<const float4*>(Wg + (size_t)i*8 + 4);
        s[0] = fmaf(xv, w0.x, s[0]); s[1] = fmaf(xv, w0.y, s[1]);
        s[2] = fmaf(xv, w0.z, s[2]); s[3] = fmaf(xv, w0.w, s[3]);
        s[4] = fmaf(xv, w1.x, s[4]); s[5] = fmaf(xv, w1.y, s[5]);
        s[6] = fmaf(xv, w1.z, s[6]); s[7] = fmaf(xv, w1.w, s[7]);
    }
    #pragma unroll
    for (int off = 16; off > 0; off >>= 1)
        #pragma unroll
        for (int j = 0; j < 8; j++)
            s[j] += __shfl_xor_sync(0xffffffffu, s[j], off);
    if (lane == 0) {
        #pragma unroll
        for (int j = 0; j < 8; j++) s[j] += bg[j];
        int i1 = 0;
        #pragma unroll
        for (int j = 1; j < 8; j++) if (s[j] > s[i1]) i1 = j;
        int i2 = -1; float b2 = -1e30f;
        #pragma unroll
        for (int j = 0; j < 8; j++) if (j != i1 && s[j] > b2) { b2 = s[j]; i2 = j; }
        float a1 = 1.f / (1.f + expf(b2 - s[i1]));
        g_m1[warp] = (unsigned char)(i1 + 1);
        g_m2[warp] = (unsigned char)(i2 + 1);
        g_a1[warp] = a1;
        g_a2[warp] = 1.f - a1;
    }
}

// ---------------- pack: 1024 threads, 2 sweep iterations ----------------
__global__ __launch_bounds__(1024) void pack_kernel()
{
    int bm = blockIdx.x;          // 0..63
    int b  = bm >> 3;
    int m  = (bm & 7) + 1;        // 1..8
    __shared__ int wsum[32];
    int tid = threadIdx.x;
    int lane = tid & 31, w = tid >> 5;
    int base = 0;
    int segbase = (b*NM_ + m - 1) * T_;
    for (int t0 = 0; t0 < T_; t0 += 1024) {
        int t = t0 + tid;
        int n = t*B_ + b;
        int sel = 0; float a = 0.f;
        int m1v = g_m1[n], m2v = g_m2[n];
        if      (m1v == m) { sel = 1; a = g_a1[n]; }
        else if (m2v == m) { sel = 1; a = g_a2[n]; }
        int incl = sel;
        #pragma unroll
        for (int off = 1; off < 32; off <<= 1) {
            int u = __shfl_up_sync(0xffffffffu, incl, off);
            if (lane >= off) incl += u;
        }
        if (lane == 31) wsum[w] = incl;
        __syncthreads();
        int woff = 0, tot = 0;
        #pragma unroll
        for (int i = 0; i < 32; i++) { int v = wsum[i]; tot += v; if (i < w) woff += v; }
        if (sel) {
            int pos = base + woff + incl - 1;
            g_tok[segbase + pos] = t;
            g_pa [segbase + pos] = a;
        }
        base += tot;
        __syncthreads();
    }
    if (tid == 0) g_cnt[b*NM_ + m - 1] = base;
}

// ---------------- fused projections: Q tiles (blocks 0..255) + KV tiles ----------------
#define KV_AP 20
#define KV_BP 136
#define KV_SMEM ((3*128*KV_AP + 3*16*KV_BP + 128) * 4)
#define Q_AP 20
#define Q_BP 72

__device__ __forceinline__ void proj_q_body(unsigned* smem, const float* bq, int bx)
{
    unsigned (*As)[64][Q_AP] = reinterpret_cast<unsigned(*)[64][Q_AP]>(smem);
    unsigned (*Bs)[16][Q_BP] = reinterpret_cast<unsigned(*)[16][Q_BP]>(smem + 3*64*Q_AP);
    int tid = threadIdx.x;
    int m0 = bx * 64;

    int aRow = (tid & 127) >> 1, aOff = (tid & 1) * 8;
    int t2 = tid & 127;
    int bK = t2 >> 3, bj = (t2 & 7) * 8;
    const unsigned* aBase = g_Xt + (size_t)(m0 + aRow)*D_ + aOff;
    const unsigned* bBase = g_Wqt + (size_t)bK*HD + bj;
    bool isA = (tid < 128);

    int lane = tid & 31, gid = lane >> 2, tig = lane & 3;
    int warpId = tid >> 5, wM = warpId & 3, wN = warpId >> 2;

    float c[4][4];
    #pragma unroll
    for (int ni = 0; ni < 4; ni++)
        #pragma unroll
        for (int j = 0; j < 4; j++) c[ni][j] = 0.f;

    // stage prologue
    #pragma unroll
    for (int s = 0; s < 2; s++) {
        int kt = s * 16;
        if (isA) {
            cp16(&As[s][aRow][aOff],     aBase + kt);
            cp16(&As[s][aRow][aOff + 4], aBase + kt + 4);
        } else {
            cp16(&Bs[s][bK][bj],     bBase + (size_t)kt*HD);
            cp16(&Bs[s][bK][bj + 4], bBase + (size_t)kt*HD + 4);
        }
        CP_COMMIT();
    }

    for (int it = 0; it < 64; it++) {
        CP_WAIT1();
        __syncthreads();
        if (it + 2 < 64) {
            int s = (it + 2) % 3, kt = (it + 2) * 16;
            if (isA) {
                cp16(&As[s][aRow][aOff],     aBase + kt);
                cp16(&As[s][aRow][aOff + 4], aBase + kt + 4);
            } else {
                cp16(&Bs[s][bK][bj],     bBase + (size_t)kt*HD);
                cp16(&Bs[s][bK][bj + 4], bBase + (size_t)kt*HD + 4);
            }
        }
        CP_COMMIT();
        int s = it % 3;
        #pragma unroll
        for (int k0 = 0; k0 < 16; k0 += 8) {
            int r = wM*16 + gid;
            unsigned a0 = As[s][r    ][k0 + tig];
            unsigned a1 = As[s][r + 8][k0 + tig];
            unsigned a2 = As[s][r    ][k0 + tig + 4];
            unsigned a3 = As[s][r + 8][k0 + tig + 4];
            #pragma unroll
            for (int ni = 0; ni < 4; ni++) {
                int cb = wN*32 + ni*8 + gid;
                unsigned b0 = Bs[s][k0 + tig    ][cb];
                unsigned b1 = Bs[s][k0 + tig + 4][cb];
                mma_tf32(c[ni], a0, a1, a2, a3, b0, b1);
            }
        }
    }

    #pragma unroll
    for (int ni = 0; ni < 4; ni++) {
        int colb = wN*32 + ni*8 + tig*2;
        float b0v = bq[colb], b1v = bq[colb + 1];
        int r1 = m0 + wM*16 + gid;
        float2 v1 = make_float2(f2tf32f(c[ni][0] + b0v), f2tf32f(c[ni][1] + b1v));
        *reinterpret_cast<float2*>(g_Q + (size_t)r1*HD + colb) = v1;
        float2 v2 = make_float2(f2tf32f(c[ni][2] + b0v), f2tf32f(c[ni][3] + b1v));
        *reinterpret_cast<float2*>(g_Q + (size_t)(r1 + 8)*HD + colb) = v2;
    }
}

__device__ __forceinline__ void proj_kv_body(unsigned* smem,
    const float* bk, const float* bv, int ci, int m, int b)
{
    int cnt = (m == 0) ? T_ : g_cnt[b*NM_ + m - 1];
    int r0 = ci << 7;
    if (r0 >= cnt) return;
    int L = cnt - r0; if (L > 128) L = 128;

    unsigned (*As)[128][KV_AP] = reinterpret_cast<unsigned(*)[128][KV_AP]>(smem);
    unsigned (*Bs)[16][KV_BP]  = reinterpret_cast<unsigned(*)[16][KV_BP]>(smem + 3*128*KV_AP);
    int* rowIdx = reinterpret_cast<int*>(smem + 3*128*KV_AP + 3*16*KV_BP);

    int tid = threadIdx.x;
    int segbase = (b*NM_ + m - 1) * T_;
    if (tid < 128) {
        int t = 0;
        if (tid < L) t = (m == 0) ? (r0 + tid) : g_tok[segbase + r0 + tid];
        rowIdx[tid] = t*B_ + b;
    }
    __syncthreads();

    int aRow = tid >> 1, aOff = (tid & 1) * 8;
    int bK   = tid >> 4;
    int bj   = (tid & 15) * 8;
    int bHalf = bj >> 6;
    int bo    = bj & 63;
    const unsigned* Wt = bHalf ? g_Wvt : g_Wkt;
    const unsigned* aBase = g_Xt + (size_t)rowIdx[aRow]*D_ + aOff;
    const unsigned* bBase = Wt + (size_t)bK*NKV + m*HD + bo;

    int lane = tid & 31, gid = lane >> 2, tig = lane & 3;
    int warpId = tid >> 5, wM = warpId & 3, wN = warpId >> 2;

    float c[2][8][4];
    #pragma unroll
    for (int mi = 0; mi < 2; mi++)
        #pragma unroll
        for (int ni = 0; ni < 8; ni++)
            #pragma unroll
            for (int j = 0; j < 4; j++) c[mi][ni][j] = 0.f;

    #pragma unroll
    for (int s = 0; s < 2; s++) {
        int kt = s * 16;
        cp16(&As[s][aRow][aOff],     aBase + kt);
        cp16(&As[s][aRow][aOff + 4], aBase + kt + 4);
        cp16(&Bs[s][bK][bj],     bBase + (size_t)kt*NKV);
        cp16(&Bs[s][bK][bj + 4], bBase + (size_t)kt*NKV + 4);
        CP_COMMIT();
    }

    for (int it = 0; it < 64; it++) {
        CP_WAIT1();
        __syncthreads();
        if (it + 2 < 64) {
            int s = (it + 2) % 3, kt = (it + 2) * 16;
            cp16(&As[s][aRow][aOff],     aBase + kt);
            cp16(&As[s][aRow][aOff + 4], aBase + kt + 4);
            cp16(&Bs[s][bK][bj],     bBase + (size_t)kt*NKV);
            cp16(&Bs[s][bK][bj + 4], bBase + (size_t)kt*NKV + 4);
        }
        CP_COMMIT();
        int s = it % 3;
        #pragma unroll
        for (int k0 = 0; k0 < 16; k0 += 8) {
            unsigned a[2][4];
            #pragma unroll
            for (int mi = 0; mi < 2; mi++) {
                int r = wM*32 + mi*16 + gid;
                a[mi][0] = As[s][r    ][k0 + tig];
                a[mi][1] = As[s][r + 8][k0 + tig];
                a[mi][2] = As[s][r    ][k0 + tig + 4];
                a[mi][3] = As[s][r + 8][k0 + tig + 4];
            }
            #pragma unroll
            for (int ni = 0; ni < 8; ni++) {
                int cb = wN*64 + ni*8 + gid;
                unsigned b0 = Bs[s][k0 + tig    ][cb];
                unsigned b1 = Bs[s][k0 + tig + 4][cb];
                mma_tf32(c[0][ni], a[0][0], a[0][1], a[0][2], a[0][3], b0, b1);
                mma_tf32(c[1][ni], a[1][0], a[1][1], a[1][2], a[1][3], b0, b1);
            }
        }
    }

    size_t segKV = ((size_t)(b*MP1 + m)*T_ + r0) * HD;
    #pragma unroll
    for (int mi = 0; mi < 2; mi++) {
        #pragma unroll
        for (int ni = 0; ni < 8; ni++) {
            int colb = wN*64 + ni*8 + tig*2;
            int half = colb >> 6;
            int cc = colb & 63;
            const float* bias = half ? bv : bk;
            float b0v = bias[m*HD + cc];
            float b1v = bias[m*HD + cc + 1];
            float* dst = (half ? g_Vp : g_Kp) + segKV + cc;
            int r1 = wM*32 + mi*16 + gid;
            if (r1 < L) {
                float2 v = make_float2(f2tf32f(c[mi][ni][0] + b0v), f2tf32f(c[mi][ni][1] + b1v));
                *reinterpret_cast<float2*>(dst + (size_t)r1*HD) = v;
            }
            int r2 = r1 + 8;
            if (r2 < L) {
                float2 v = make_float2(f2tf32f(c[mi][ni][2] + b0v), f2tf32f(c[mi][ni][3] + b1v));
                *reinterpret_cast<float2*>(dst + (size_t)r2*HD) = v;
            }
        }
    }
}

__global__ __launch_bounds__(256, 2) void proj_kernel(
    const float* __restrict__ bq, const float* __restrict__ bk, const float* __restrict__ bv)
{
    extern __shared__ __align__(16) unsigned smem[];
    int bx = blockIdx.x;
    if (bx < 256) {
        proj_q_body(smem, bq, bx);
    } else {
        int idx = bx - 256;
        int ci = idx & 15;
        int rem = idx >> 4;
        int m = rem % MP1, b = rem / MP1;
        proj_kv_body(smem, bk, bv, ci, m, b);
    }
}

// ---------------- per-chunk G = K^T V via tf32 mma ----------------
#define CP_ 68
__global__ __launch_bounds__(256) void chunk_g_kernel()
{
    int ci = blockIdx.x, m = blockIdx.y, b = blockIdx.z;
    int cnt = (m == 0) ? T_ : g_cnt[b*NM_ + m - 1];
    if ((ci << 6) >= cnt) return;
    int L = cnt - (ci << 6); if (L > 64) L = 64;
    __shared__ __align__(16) float Ks[64][CP_];
    __shared__ __align__(16) float Vs[64][CP_];
    int tid = threadIdx.x;
    size_t segp = ((size_t)(b*MP1 + m)*T_ + (ci << 6)) * HD;
    {
        int r = tid >> 2, q4 = tid & 3;
        bool valid = r < L;
        #pragma unroll
        for (int j = 0; j < 4; j++) {
            int c = q4*16 + j*4;
            float4 kv = valid ? *reinterpret_cast<const float4*>(g_Kp + segp + (size_t)r*HD + c) : make_float4(0,0,0,0);
            float4 vv = valid ? *reinterpret_cast<const float4*>(g_Vp + segp + (size_t)r*HD + c) : make_float4(0,0,0,0);
            *reinterpret_cast<float4*>(&Ks[r][c]) = kv;
            *reinterpret_cast<float4*>(&Vs[r][c]) = vv;
        }
    }
    __syncthreads();
    int lane = tid & 31, gid = lane >> 2, tig = lane & 3;
    int warpId = tid >> 5, wM = warpId & 3, wN = warpId >> 2;
    int i0 = wM*16, j0 = wN*32;

    float c[4][4];
    #pragma unroll
    for (int ni = 0; ni < 4; ni++)
        #pragma unroll
        for (int j = 0; j < 4; j++) c[ni][j] = 0.f;

    #pragma unroll
    for (int k0 = 0; k0 < 64; k0 += 8) {
        unsigned a0 = __float_as_uint(Ks[k0 + tig    ][i0 + gid]);
        unsigned a1 = __float_as_uint(Ks[k0 + tig    ][i0 + gid + 8]);
        unsigned a2 = __float_as_uint(Ks[k0 + tig + 4][i0 + gid]);
        unsigned a3 = __float_as_uint(Ks[k0 + tig + 4][i0 + gid + 8]);
        #pragma unroll
        for (int ni = 0; ni < 4; ni++) {
            int cb = j0 + ni*8 + gid;
            unsigned b0 = __float_as_uint(Vs[k0 + tig    ][cb]);
            unsigned b1 = __float_as_uint(Vs[k0 + tig + 4][cb]);
            mma_tf32(c[ni], a0, a1, a2, a3, b0, b1);
        }
    }

    float* Gp = g_G + (size_t)((b*MP1 + m)*32 + ci) * 4096;
    #pragma unroll
    for (int ni = 0; ni < 4; ni++) {
        int j = j0 + ni*8 + tig*2;
        *reinterpret_cast<float2*>(Gp + (i0 + gid)*64 + j)     = make_float2(c[ni][0], c[ni][1]);
        *reinterpret_cast<float2*>(Gp + (i0 + gid + 8)*64 + j) = make_float2(c[ni][2], c[ni][3]);
    }
}

// ---------------- per-segment prefix, 16 slices per (b,m), tf32-rounded S ----------------
__global__ __launch_bounds__(256) void prefix_kernel(const float* __restrict__ M0)
{
    int bm = blockIdx.x;               // 0..71
    int b = bm / MP1, m = bm % MP1;
    int cnt = (m == 0) ? T_ : g_cnt[b*NM_ + m - 1];
    int nch = (cnt + 63) >> 6;
    int idx = blockIdx.y * 256 + threadIdx.x;   // 0..4095
    float st = M0[idx];
    size_t base = (size_t)(bm * 32) * 4096;
    for (int ci = 0; ci < nch; ci++) {
        size_t off = base + (size_t)ci * 4096 + idx;
        g_S[off] = f2tf32f(st);
        st += g_G[off];
    }
}

// ---------------- per-chunk output via tf32 mma: O = tril(QK^T)V + Q S ----------------
#define OP_ 68
#define O_SMEM (3*64*OP_*4)
__global__ __launch_bounds__(256, 2) void chunk_o_kernel(float* __restrict__ out)
{
    int ci = blockIdx.x, m = blockIdx.y, b = blockIdx.z;
    int cnt = (m == 0) ? T_ : g_cnt[b*NM_ + m - 1];
    if ((ci << 6) >= cnt) return;
    int L = cnt - (ci << 6); if (L > 64) L = 64;

    extern __shared__ __align__(16) float sm[];
    float (*QS)[OP_] = reinterpret_cast<float(*)[OP_]>(sm);            // Q, then S
    float (*KP)[OP_] = reinterpret_cast<float(*)[OP_]>(sm + 64*OP_);   // K, then P
    float (*Vs)[OP_] = reinterpret_cast<float(*)[OP_]>(sm + 2*64*OP_); // V

    int tid = threadIdx.x;
    int segbase = (m == 0) ? 0 : (b*NM_ + m - 1)*T_;
    size_t segp = ((size_t)(b*MP1 + m)*T_ + (ci << 6)) * HD;
    {
        int r = tid >> 2, q4 = tid & 3;
        bool valid = r < L;
        const float* qs = g_Q;
        if (valid) {
            int i = (ci << 6) + r;
            int t = (m == 0) ? i : g_tok[segbase + i];
            qs = g_Q + ((size_t)t*B_ + b)*HD;
        }
        #pragma unroll
        for (int j = 0; j < 4; j++) {
            int c = q4*16 + j*4;
            float4 qv = valid ? *reinterpret_cast<const float4*>(qs + c) : make_float4(0,0,0,0);
            float4 kv = valid ? *reinterpret_cast<const float4*>(g_Kp + segp + (size_t)r*HD + c) : make_float4(0,0,0,0);
            float4 vv = valid ? *reinterpret_cast<const float4*>(g_Vp + segp + (size_t)r*HD + c) : make_float4(0,0,0,0);
            *reinterpret_cast<float4*>(&QS[r][c]) = qv;
            *reinterpret_cast<float4*>(&KP[r][c]) = kv;
            *reinterpret_cast<float4*>(&Vs[r][c]) = vv;
        }
    }
    __syncthreads();

    int lane = tid & 31, gid = lane >> 2, tig = lane & 3;
    int warpId = tid >> 5, wM = warpId & 3, wN = warpId >> 2;
    int r0 = wM*16, n0 = wN*32;

    // Q fragments (k = feature), reused by stage 1 and stage 3
    unsigned aQ[8][4];
    #pragma unroll
    for (int ks = 0; ks < 8; ks++) {
        int k0 = ks*8;
        aQ[ks][0] = __float_as_uint(QS[r0 + gid    ][k0 + tig]);
        aQ[ks][1] = __float_as_uint(QS[r0 + gid + 8][k0 + tig]);
        aQ[ks][2] = __float_as_uint(QS[r0 + gid    ][k0 + tig + 4]);
        aQ[ks][3] = __float_as_uint(QS[r0 + gid + 8][k0 + tig + 4]);
    }

    // stage 1: P = Q K^T
    float p[4][4];
    #pragma unroll
    for (int ni = 0; ni < 4; ni++)
        #pragma unroll
        for (int j = 0; j < 4; j++) p[ni][j] = 0.f;
    #pragma unroll
    for (int ks = 0; ks < 8; ks++) {
        int k0 = ks*8;
        #pragma unroll
        for (int ni = 0; ni < 4; ni++) {
            int cb = n0 + ni*8 + gid;
            unsigned b0 = __float_as_uint(KP[cb][k0 + tig]);
            unsigned b1 = __float_as_uint(KP[cb][k0 + tig + 4]);
            mma_tf32(p[ni], aQ[ks][0], aQ[ks][1], aQ[ks][2], aQ[ks][3], b0, b1);
        }
    }
    __syncthreads();

    // write masked tf32 P over K; load S over Q
    #pragma unroll
    for (int ni = 0; ni < 4; ni++) {
        int col = n0 + ni*8 + tig*2;
        int row1 = r0 + gid, row2 = r0 + gid + 8;
        KP[row1][col]     = (col     <= row1) ? f2tf32f(p[ni][0]) : 0.f;
        KP[row1][col + 1] = (col + 1 <= row1) ? f2tf32f(p[ni][1]) : 0.f;
        KP[row2][col]     = (col     <= row2) ? f2tf32f(p[ni][2]) : 0.f;
        KP[row2][col + 1] = (col + 1 <= row2) ? f2tf32f(p[ni][3]) : 0.f;
    }
    {
        int r = tid >> 2, q4 = tid & 3;
        const float* Sp = g_S + (size_t)((b*MP1 + m)*32 + ci) * 4096;
        #pragma unroll
        for (int j = 0; j < 4; j++) {
            int c = q4*16 + j*4;
            *reinterpret_cast<float4*>(&QS[r][c]) = *reinterpret_cast<const float4*>(Sp + r*64 + c);
        }
    }
    __syncthreads();

    // stages 2+3: O = P V + Q S
    float o[4][4];
    #pragma unroll
    for (int ni = 0; ni < 4; ni++)
        #pragma unroll
        for (int j = 0; j < 4; j++) o[ni][j] = 0.f;
    #pragma unroll
    for (int ks = 0; ks < 8; ks++) {
        int k0 = ks*8;
        unsigned a0 = __float_as_uint(KP[r0 + gid    ][k0 + tig]);
        unsigned a1 = __float_as_uint(KP[r0 + gid + 8][k0 + tig]);
        unsigned a2 = __float_as_uint(KP[r0 + gid    ][k0 + tig + 4]);
        unsigned a3 = __float_as_uint(KP[r0 + gid + 8][k0 + tig + 4]);
        #pragma unroll
        for (int ni = 0; ni < 4; ni++) {
            int cb = n0 + ni*8 + gid;
            unsigned b0 = __float_as_uint(Vs[k0 + tig    ][cb]);
            unsigned b1 = __float_as_uint(Vs[k0 + tig + 4][cb]);
            mma_tf32(o[ni], a0, a1, a2, a3, b0, b1);
            unsigned s0 = __float_as_uint(QS[k0 + tig    ][cb]);
            unsigned s1 = __float_as_uint(QS[k0 + tig + 4][cb]);
            mma_tf32(o[ni], aQ[ks][0], aQ[ks][1], aQ[ks][2], aQ[ks][3], s0, s1);
        }
    }

    // epilogue: out[t,b,col..col+1] += alpha * o
    #pragma unroll
    for (int rr = 0; rr < 2; rr++) {
        int r = r0 + gid + rr*8;
        if (r >= L) continue;
        int idx = (ci << 6) + r;
        int t; float alpha;
        if (m == 0) { t = idx; alpha = 1.f; }
        else        { t = g_tok[segbase + idx]; alpha = g_pa[segbase + idx]; }
        float* op = out + ((size_t)t*B_ + b)*HD;
        #pragma unroll
        for (int ni = 0; ni < 4; ni++) {
            int col = n0 + ni*8 + tig*2;
            atomicAdd(op + col,     alpha * o[ni][rr*2]);
            atomicAdd(op + col + 1, alpha * o[ni][rr*2 + 1]);
        }
    }
}

// ---------------- launch ----------------
extern "C" void kernel_launch(void* const* d_in, const int* in_sizes, int n_in,
                              void* d_out, int out_size)
{
    const float* X  = (const float*)d_in[0];
    const float* M0 = (const float*)d_in[1];
    const float* bq = (const float*)d_in[3];
    const float* Wk = (const float*)d_in[4];
    const float* bk = (const float*)d_in[5];
    const float* Wv = (const float*)d_in[6];
    const float* bv = (const float*)d_in[7];
    const float* Wg = (const float*)d_in[8];
    const float* bg = (const float*)d_in[9];
    const float* Wq = (const float*)d_in[2];
    float* out = (float*)d_out;

    cudaFuncSetAttribute(proj_kernel,
                         cudaFuncAttributeMaxDynamicSharedMemorySize, KV_SMEM);
    cudaFuncSetAttribute(chunk_o_kernel,
                         cudaFuncAttributeMaxDynamicSharedMemorySize, O_SMEM);

    prep_kernel<<<GATE_BLKS + ZERO_BLKS + WCONV_BLKS, 256>>>(X, Wg, bg, Wq, Wk, Wv, out);
    pack_kernel<<<64, 1024>>>();
    proj_kernel<<<256 + 16*MP1*B_, 256, KV_SMEM>>>(bq, bk, bv);
    chunk_g_kernel<<<dim3(32, MP1, B_), 256>>>();
    prefix_kernel<<<dim3(B_*MP1, 16), 256>>>(M0);
    chunk_o_kernel<<<dim3(32, MP1, B_), 256, O_SMEM>>>(out);
}

// round 9
// speedup vs baseline: 5.6991x; 1.0694x over previous
#include <cuda_runtime.h>
#include <math.h>

#define T_   2048
#define B_   8
#define D_   1024
#define HD   64      // d
#define NM_  8
#define MP1  9
#define NT   (T_*B_)     // 16384 tokens
#define NKV  576         // Mp1 * d

// ---------------- static device scratch ----------------
__device__ float g_Q[NT*HD];                                // tf32-valued fp32
__device__ float g_Kp[(size_t)B_*MP1*T_*HD];                // packed K per (b,m), tf32-valued
__device__ float g_Vp[(size_t)B_*MP1*T_*HD];                // packed V per (b,m), tf32-valued
#define NSLOT (B_*MP1*32)
__device__ float g_G[(size_t)NSLOT*HD*HD];                  // per-chunk K^T V (fp32)
__device__ float g_S[(size_t)NSLOT*HD*HD];                  // chunk start state (tf32-valued)
__device__ int   g_tok[B_*NM_*T_];
__device__ float g_pa [B_*NM_*T_];
__device__ int   g_cnt[B_*NM_];
__device__ unsigned char g_m1[NT], g_m2[NT];
__device__ float g_a1[NT], g_a2[NT];
__device__ unsigned g_Xt[(size_t)NT*D_];                    // X in tf32 bits
__device__ unsigned g_Wqt[D_*HD];
__device__ unsigned g_Wkt[D_*NKV];
__device__ unsigned g_Wvt[D_*NKV];

// ---------------- tf32 mma helpers ----------------
__device__ __forceinline__ unsigned f2tf32(float f) {
    unsigned u;
    asm("cvt.rna.tf32.f32 %0, %1;" : "=r"(u) : "f"(f));
    return u;
}
__device__ __forceinline__ float f2tf32f(float f) { return __uint_as_float(f2tf32(f)); }
__device__ __forceinline__ void mma_tf32(float* c,
    unsigned a0, unsigned a1, unsigned a2, unsigned a3,
    unsigned b0, unsigned b1)
{
    asm volatile(
        "mma.sync.aligned.m16n8k8.row.col.f32.tf32.tf32.f32 "
        "{%0,%1,%2,%3}, {%4,%5,%6,%7}, {%8,%9}, {%0,%1,%2,%3};"
        : "+f"(c[0]), "+f"(c[1]), "+f"(c[2]), "+f"(c[3])
        : "r"(a0), "r"(a1), "r"(a2), "r"(a3), "r"(b0), "r"(b1));
}
__device__ __forceinline__ void cp16(void* dst, const void* src) {
    unsigned s = (unsigned)__cvta_generic_to_shared(dst);
    asm volatile("cp.async.cg.shared.global [%0], [%1], 16;" :: "r"(s), "l"(src));
}
#define CP_COMMIT() asm volatile("cp.async.commit_group;" ::)
#define CP_WAIT1()  asm volatile("cp.async.wait_group 1;" ::)
#define CP_WAIT0()  asm volatile("cp.async.wait_group 0;" ::)

// ---------------- fused prep: gate (+tf32 X) | zero out | weight convert ----------------
#define GATE_BLKS 2048
#define ZERO_BLKS 1024
#define WCONV_BLKS 2304
__global__ __launch_bounds__(256) void prep_kernel(
    const float* __restrict__ X, const float* __restrict__ Wg, const float* __restrict__ bg,
    const float* __restrict__ Wq, const float* __restrict__ Wk, const float* __restrict__ Wv,
    float* __restrict__ out)
{
    int bx = blockIdx.x;
    if (bx >= GATE_BLKS) {
        if (bx < GATE_BLKS + ZERO_BLKS) {
            int i = (bx - GATE_BLKS) * 256 + threadIdx.x;
            reinterpret_cast<float4*>(out)[i] = make_float4(0.f, 0.f, 0.f, 0.f);
        } else {
            int i = (bx - GATE_BLKS - ZERO_BLKS) * 256 + threadIdx.x;
            if (i < D_*HD) g_Wqt[i] = f2tf32(Wq[i]);
            g_Wkt[i] = f2tf32(Wk[i]);
            g_Wvt[i] = f2tf32(Wv[i]);
        }
        return;
    }
    int warp = (bx * 256 + threadIdx.x) >> 5;
    int lane = threadIdx.x & 31;
    const float* x = X + (size_t)warp * D_;
    float s[8];
    #pragma unroll
    for (int j = 0; j < 8; j++) s[j] = 0.f;
    for (int i = lane; i < D_; i += 32) {
        float xv = x[i];
        g_Xt[(size_t)warp*D_ + i] = f2tf32(xv);
        float4 w0 = *reinterpret_cast<const float4*>(Wg + (size_t)i*8);
        float4 w1 = *reinterpret_cast<const float4*>(Wg + (size_t)i*8 + 4);
        s[0] = fmaf(xv, w0.x, s[0]); s[1] = fmaf(xv, w0.y, s[1]);
        s[2] = fmaf(xv, w0.z, s[2]); s[3] = fmaf(xv, w0.w, s[3]);
        s[4] = fmaf(xv, w1.x, s[4]); s[5] = fmaf(xv, w1.y, s[5]);
        s[6] = fmaf(xv, w1.z, s[6]); s[7] = fmaf(xv, w1.w, s[7]);
    }
    #pragma unroll
    for (int off = 16; off > 0; off >>= 1)
        #pragma unroll
        for (int j = 0; j < 8; j++)
            s[j] += __shfl_xor_sync(0xffffffffu, s[j], off);
    if (lane == 0) {
        #pragma unroll
        for (int j = 0; j < 8; j++) s[j] += bg[j];
        int i1 = 0;
        #pragma unroll
        for (int j = 1; j < 8; j++) if (s[j] > s[i1]) i1 = j;
        int i2 = -1; float b2 = -1e30f;
        #pragma unroll
        for (int j = 0; j < 8; j++) if (j != i1 && s[j] > b2) { b2 = s[j]; i2 = j; }
        float a1 = 1.f / (1.f + expf(b2 - s[i1]));
        g_m1[warp] = (unsigned char)(i1 + 1);
        g_m2[warp] = (unsigned char)(i2 + 1);
        g_a1[warp] = a1;
        g_a2[warp] = 1.f - a1;
    }
}

// ---------------- pack: 1024 threads, 2 sweep iterations ----------------
__global__ __launch_bounds__(1024) void pack_kernel()
{
    int bm = blockIdx.x;          // 0..63
    int b  = bm >> 3;
    int m  = (bm & 7) + 1;        // 1..8
    __shared__ int wsum[32];
    int tid = threadIdx.x;
    int lane = tid & 31, w = tid >> 5;
    int base = 0;
    int segbase = (b*NM_ + m - 1) * T_;
    for (int t0 = 0; t0 < T_; t0 += 1024) {
        int t = t0 + tid;
        int n = t*B_ + b;
        int sel = 0; float a = 0.f;
        int m1v = g_m1[n], m2v = g_m2[n];
        if      (m1v == m) { sel = 1; a = g_a1[n]; }
        else if (m2v == m) { sel = 1; a = g_a2[n]; }
        int incl = sel;
        #pragma unroll
        for (int off = 1; off < 32; off <<= 1) {
            int u = __shfl_up_sync(0xffffffffu, incl, off);
            if (lane >= off) incl += u;
        }
        if (lane == 31) wsum[w] = incl;
        __syncthreads();
        int woff = 0, tot = 0;
        #pragma unroll
        for (int i = 0; i < 32; i++) { int v = wsum[i]; tot += v; if (i < w) woff += v; }
        if (sel) {
            int pos = base + woff + incl - 1;
            g_tok[segbase + pos] = t;
            g_pa [segbase + pos] = a;
        }
        base += tot;
        __syncthreads();
    }
    if (tid == 0) g_cnt[b*NM_ + m - 1] = base;
}

// ---------------- fused projections: KV tiles (blocks 0..1151) + Q tiles ----------------
#define KV_AP 20
#define KV_BP 136
#define KV_SMEM ((3*128*KV_AP + 3*16*KV_BP + 128) * 4)
#define Q_AP 20
#define Q_BP 72
#define GP_ 68

__device__ __forceinline__ void proj_q_body(unsigned* smem, const float* bq, int bx)
{
    unsigned (*As)[64][Q_AP] = reinterpret_cast<unsigned(*)[64][Q_AP]>(smem);
    unsigned (*Bs)[16][Q_BP] = reinterpret_cast<unsigned(*)[16][Q_BP]>(smem + 3*64*Q_AP);
    int tid = threadIdx.x;
    int m0 = bx * 64;

    int aRow = (tid & 127) >> 1, aOff = (tid & 1) * 8;
    int t2 = tid & 127;
    int bK = t2 >> 3, bj = (t2 & 7) * 8;
    const unsigned* aBase = g_Xt + (size_t)(m0 + aRow)*D_ + aOff;
    const unsigned* bBase = g_Wqt + (size_t)bK*HD + bj;
    bool isA = (tid < 128);

    int lane = tid & 31, gid = lane >> 2, tig = lane & 3;
    int warpId = tid >> 5, wM = warpId & 3, wN = warpId >> 2;

    float c[4][4];
    #pragma unroll
    for (int ni = 0; ni < 4; ni++)
        #pragma unroll
        for (int j = 0; j < 4; j++) c[ni][j] = 0.f;

    #pragma unroll
    for (int s = 0; s < 2; s++) {
        int kt = s * 16;
        if (isA) {
            cp16(&As[s][aRow][aOff],     aBase + kt);
            cp16(&As[s][aRow][aOff + 4], aBase + kt + 4);
        } else {
            cp16(&Bs[s][bK][bj],     bBase + (size_t)kt*HD);
            cp16(&Bs[s][bK][bj + 4], bBase + (size_t)kt*HD + 4);
        }
        CP_COMMIT();
    }

    for (int it = 0; it < 64; it++) {
        CP_WAIT1();
        __syncthreads();
        if (it + 2 < 64) {
            int s = (it + 2) % 3, kt = (it + 2) * 16;
            if (isA) {
                cp16(&As[s][aRow][aOff],     aBase + kt);
                cp16(&As[s][aRow][aOff + 4], aBase + kt + 4);
            } else {
                cp16(&Bs[s][bK][bj],     bBase + (size_t)kt*HD);
                cp16(&Bs[s][bK][bj + 4], bBase + (size_t)kt*HD + 4);
            }
        }
        CP_COMMIT();
        int s = it % 3;
        #pragma unroll
        for (int k0 = 0; k0 < 16; k0 += 8) {
            int r = wM*16 + gid;
            unsigned a0 = As[s][r    ][k0 + tig];
            unsigned a1 = As[s][r + 8][k0 + tig];
            unsigned a2 = As[s][r    ][k0 + tig + 4];
            unsigned a3 = As[s][r + 8][k0 + tig + 4];
            #pragma unroll
            for (int ni = 0; ni < 4; ni++) {
                int cb = wN*32 + ni*8 + gid;
                unsigned b0 = Bs[s][k0 + tig    ][cb];
                unsigned b1 = Bs[s][k0 + tig + 4][cb];
                mma_tf32(c[ni], a0, a1, a2, a3, b0, b1);
            }
        }
    }

    #pragma unroll
    for (int ni = 0; ni < 4; ni++) {
        int colb = wN*32 + ni*8 + tig*2;
        float b0v = bq[colb], b1v = bq[colb + 1];
        int r1 = m0 + wM*16 + gid;
        float2 v1 = make_float2(f2tf32f(c[ni][0] + b0v), f2tf32f(c[ni][1] + b1v));
        *reinterpret_cast<float2*>(g_Q + (size_t)r1*HD + colb) = v1;
        float2 v2 = make_float2(f2tf32f(c[ni][2] + b0v), f2tf32f(c[ni][3] + b1v));
        *reinterpret_cast<float2*>(g_Q + (size_t)(r1 + 8)*HD + colb) = v2;
    }
}

__device__ __forceinline__ void proj_kv_body(unsigned* smem,
    const float* bk, const float* bv, int ci, int m, int b)
{
    int cnt = (m == 0) ? T_ : g_cnt[b*NM_ + m - 1];
    int r0 = ci << 7;
    if (r0 >= cnt) return;
    int L = cnt - r0; if (L > 128) L = 128;

    unsigned (*As)[128][KV_AP] = reinterpret_cast<unsigned(*)[128][KV_AP]>(smem);
    unsigned (*Bs)[16][KV_BP]  = reinterpret_cast<unsigned(*)[16][KV_BP]>(smem + 3*128*KV_AP);
    int* rowIdx = reinterpret_cast<int*>(smem + 3*128*KV_AP + 3*16*KV_BP);

    int tid = threadIdx.x;
    int segbase = (b*NM_ + m - 1) * T_;
    if (tid < 128) {
        int t = 0;
        if (tid < L) t = (m == 0) ? (r0 + tid) : g_tok[segbase + r0 + tid];
        rowIdx[tid] = t*B_ + b;
    }
    __syncthreads();

    int aRow = tid >> 1, aOff = (tid & 1) * 8;
    int bK   = tid >> 4;
    int bj   = (tid & 15) * 8;
    int bHalf = bj >> 6;
    int bo    = bj & 63;
    const unsigned* Wt = bHalf ? g_Wvt : g_Wkt;
    const unsigned* aBase = g_Xt + (size_t)rowIdx[aRow]*D_ + aOff;
    const unsigned* bBase = Wt + (size_t)bK*NKV + m*HD + bo;

    int lane = tid & 31, gid = lane >> 2, tig = lane & 3;
    int warpId = tid >> 5, wM = warpId & 3, wN = warpId >> 2;

    float c[2][8][4];
    #pragma unroll
    for (int mi = 0; mi < 2; mi++)
        #pragma unroll
        for (int ni = 0; ni < 8; ni++)
            #pragma unroll
            for (int j = 0; j < 4; j++) c[mi][ni][j] = 0.f;

    #pragma unroll
    for (int s = 0; s < 2; s++) {
        int kt = s * 16;
        cp16(&As[s][aRow][aOff],     aBase + kt);
        cp16(&As[s][aRow][aOff + 4], aBase + kt + 4);
        cp16(&Bs[s][bK][bj],     bBase + (size_t)kt*NKV);
        cp16(&Bs[s][bK][bj + 4], bBase + (size_t)kt*NKV + 4);
        CP_COMMIT();
    }

    for (int it = 0; it < 64; it++) {
        CP_WAIT1();
        __syncthreads();
        if (it + 2 < 64) {
            int s = (it + 2) % 3, kt = (it + 2) * 16;
            cp16(&As[s][aRow][aOff],     aBase + kt);
            cp16(&As[s][aRow][aOff + 4], aBase + kt + 4);
            cp16(&Bs[s][bK][bj],     bBase + (size_t)kt*NKV);
            cp16(&Bs[s][bK][bj + 4], bBase + (size_t)kt*NKV + 4);
        }
        CP_COMMIT();
        int s = it % 3;
        #pragma unroll
        for (int k0 = 0; k0 < 16; k0 += 8) {
            unsigned a[2][4];
            #pragma unroll
            for (int mi = 0; mi < 2; mi++) {
                int r = wM*32 + mi*16 + gid;
                a[mi][0] = As[s][r    ][k0 + tig];
                a[mi][1] = As[s][r + 8][k0 + tig];
                a[mi][2] = As[s][r    ][k0 + tig + 4];
                a[mi][3] = As[s][r + 8][k0 + tig + 4];
            }
            #pragma unroll
            for (int ni = 0; ni < 8; ni++) {
                int cb = wN*64 + ni*8 + gid;
                unsigned b0 = Bs[s][k0 + tig    ][cb];
                unsigned b1 = Bs[s][k0 + tig + 4][cb];
                mma_tf32(c[0][ni], a[0][0], a[0][1], a[0][2], a[0][3], b0, b1);
                mma_tf32(c[1][ni], a[1][0], a[1][1], a[1][2], a[1][3], b0, b1);
            }
        }
    }

    // ---- global K/V stores ----
    size_t segKV = ((size_t)(b*MP1 + m)*T_ + r0) * HD;
    #pragma unroll
    for (int mi = 0; mi < 2; mi++) {
        #pragma unroll
        for (int ni = 0; ni < 8; ni++) {
            int colb = wN*64 + ni*8 + tig*2;
            int half = colb >> 6;
            int cc = colb & 63;
            const float* bias = half ? bv : bk;
            float b0v = bias[m*HD + cc];
            float b1v = bias[m*HD + cc + 1];
            float* dst = (half ? g_Vp : g_Kp) + segKV + cc;
            int r1 = wM*32 + mi*16 + gid;
            if (r1 < L) {
                float2 v = make_float2(f2tf32f(c[mi][ni][0] + b0v), f2tf32f(c[mi][ni][1] + b1v));
                *reinterpret_cast<float2*>(dst + (size_t)r1*HD) = v;
            }
            int r2 = r1 + 8;
            if (r2 < L) {
                float2 v = make_float2(f2tf32f(c[mi][ni][2] + b0v), f2tf32f(c[mi][ni][3] + b1v));
                *reinterpret_cast<float2*>(dst + (size_t)r2*HD) = v;
            }
        }
    }

    // ---- fused G = K^T V per 64-chunk (reuses pipeline smem) ----
    float* fb = reinterpret_cast<float*>(smem);
    float (*Ks)[GP_] = reinterpret_cast<float(*)[GP_]>(fb);
    float (*Vs)[GP_] = reinterpret_cast<float(*)[GP_]>(fb + 64*GP_);
    int nchunk = (L + 63) >> 6;

    for (int cp = 0; cp < nchunk; cp++) {
        __syncthreads();   // pipeline smem (or previous pass) no longer in use
        if ((wM >> 1) == cp) {
            int lrBase = (wM & 1) * 32;
            #pragma unroll
            for (int mi = 0; mi < 2; mi++) {
                #pragma unroll
                for (int ni = 0; ni < 8; ni++) {
                    int colb = wN*64 + ni*8 + tig*2;
                    int half = colb >> 6;
                    int cc = colb & 63;
                    const float* bias = half ? bv : bk;
                    float b0v = bias[m*HD + cc];
                    float b1v = bias[m*HD + cc + 1];
                    float (*Ts)[GP_] = half ? Vs : Ks;
                    int lr1 = lrBase + mi*16 + gid;
                    int gr1 = cp*64 + lr1;
                    Ts[lr1][cc]     = (gr1 < L) ? f2tf32f(c[mi][ni][0] + b0v) : 0.f;
                    Ts[lr1][cc + 1] = (gr1 < L) ? f2tf32f(c[mi][ni][1] + b1v) : 0.f;
                    int lr2 = lr1 + 8, gr2 = gr1 + 8;
                    Ts[lr2][cc]     = (gr2 < L) ? f2tf32f(c[mi][ni][2] + b0v) : 0.f;
                    Ts[lr2][cc + 1] = (gr2 < L) ? f2tf32f(c[mi][ni][3] + b1v) : 0.f;
                }
            }
        }
        __syncthreads();

        float g[4][4];
        #pragma unroll
        for (int ni = 0; ni < 4; ni++)
            #pragma unroll
            for (int j = 0; j < 4; j++) g[ni][j] = 0.f;
        int i0 = wM*16, j0 = wN*32;
        #pragma unroll
        for (int k0 = 0; k0 < 64; k0 += 8) {
            unsigned a0 = __float_as_uint(Ks[k0 + tig    ][i0 + gid]);
            unsigned a1 = __float_as_uint(Ks[k0 + tig    ][i0 + gid + 8]);
            unsigned a2 = __float_as_uint(Ks[k0 + tig + 4][i0 + gid]);
            unsigned a3 = __float_as_uint(Ks[k0 + tig + 4][i0 + gid + 8]);
            #pragma unroll
            for (int ni = 0; ni < 4; ni++) {
                int cb = j0 + ni*8 + gid;
                unsigned b0 = __float_as_uint(Vs[k0 + tig    ][cb]);
                unsigned b1 = __float_as_uint(Vs[k0 + tig + 4][cb]);
                mma_tf32(g[ni], a0, a1, a2, a3, b0, b1);
            }
        }
        float* Gp = g_G + (size_t)((b*MP1 + m)*32 + ci*2 + cp) * 4096;
        #pragma unroll
        for (int ni = 0; ni < 4; ni++) {
            int j = j0 + ni*8 + tig*2;
            *reinterpret_cast<float2*>(Gp + (i0 + gid)*64 + j)     = make_float2(g[ni][0], g[ni][1]);
            *reinterpret_cast<float2*>(Gp + (i0 + gid + 8)*64 + j) = make_float2(g[ni][2], g[ni][3]);
        }
    }
}

#define KV_BLKS (16*MP1*B_)
__global__ __launch_bounds__(256, 2) void proj_kernel(
    const float* __restrict__ bq, const float* __restrict__ bk, const float* __restrict__ bv)
{
    extern __shared__ __align__(16) unsigned smem[];
    int bx = blockIdx.x;
    if (bx < KV_BLKS) {
        int ci = bx & 15;
        int rem = bx >> 4;
        int m = rem % MP1, b = rem / MP1;
        proj_kv_body(smem, bk, bv, ci, m, b);
    } else {
        proj_q_body(smem, bq, bx - KV_BLKS);
    }
}

// ---------------- per-segment prefix, 16 slices per (b,m), tf32-rounded S ----------------
__global__ __launch_bounds__(256) void prefix_kernel(const float* __restrict__ M0)
{
    int bm = blockIdx.x;               // 0..71
    int b = bm / MP1, m = bm % MP1;
    int cnt = (m == 0) ? T_ : g_cnt[b*NM_ + m - 1];
    int nch = (cnt + 63) >> 6;
    int idx = blockIdx.y * 256 + threadIdx.x;   // 0..4095
    float st = M0[idx];
    size_t base = (size_t)(bm * 32) * 4096;
    for (int ci = 0; ci < nch; ci++) {
        size_t off = base + (size_t)ci * 4096 + idx;
        g_S[off] = f2tf32f(st);
        st += g_G[off];
    }
}

// ---------------- per-chunk output via tf32 mma: O = tril(QK^T)V + Q S ----------------
#define OP_ 68
#define O_SMEM (4*64*OP_*4)
__global__ __launch_bounds__(256, 2) void chunk_o_kernel(float* __restrict__ out)
{
    int ci = blockIdx.x, m = blockIdx.y, b = blockIdx.z;
    int cnt = (m == 0) ? T_ : g_cnt[b*NM_ + m - 1];
    if ((ci << 6) >= cnt) return;
    int L = cnt - (ci << 6); if (L > 64) L = 64;

    extern __shared__ __align__(16) float sm[];
    float (*QS)[OP_] = reinterpret_cast<float(*)[OP_]>(sm);            // Q
    float (*KP)[OP_] = reinterpret_cast<float(*)[OP_]>(sm + 64*OP_);   // K, then P
    float (*Vs)[OP_] = reinterpret_cast<float(*)[OP_]>(sm + 2*64*OP_); // V
    float (*Ss)[OP_] = reinterpret_cast<float(*)[OP_]>(sm + 3*64*OP_); // S (cp.async prefetch)

    int tid = threadIdx.x;
    int segbase = (m == 0) ? 0 : (b*NM_ + m - 1)*T_;
    size_t segp = ((size_t)(b*MP1 + m)*T_ + (ci << 6)) * HD;

    // prefetch S (no dependency on stage 1)
    {
        const float* Sp = g_S + (size_t)((b*MP1 + m)*32 + ci) * 4096;
        #pragma unroll
        for (int i = 0; i < 4; i++) {
            int k = tid + i*256;
            int r = k >> 4, cc = (k & 15) * 4;
            cp16(&Ss[r][cc], Sp + r*64 + cc);
        }
        CP_COMMIT();
    }

    {
        int r = tid >> 2, q4 = tid & 3;
        bool valid = r < L;
        const float* qs = g_Q;
        if (valid) {
            int i = (ci << 6) + r;
            int t = (m == 0) ? i : g_tok[segbase + i];
            qs = g_Q + ((size_t)t*B_ + b)*HD;
        }
        #pragma unroll
        for (int j = 0; j < 4; j++) {
            int c = q4*16 + j*4;
            float4 qv = valid ? *reinterpret_cast<const float4*>(qs + c) : make_float4(0,0,0,0);
            float4 kv = valid ? *reinterpret_cast<const float4*>(g_Kp + segp + (size_t)r*HD + c) : make_float4(0,0,0,0);
            float4 vv = valid ? *reinterpret_cast<const float4*>(g_Vp + segp + (size_t)r*HD + c) : make_float4(0,0,0,0);
            *reinterpret_cast<float4*>(&QS[r][c]) = qv;
            *reinterpret_cast<float4*>(&KP[r][c]) = kv;
            *reinterpret_cast<float4*>(&Vs[r][c]) = vv;
        }
    }
    __syncthreads();

    int lane = tid & 31, gid = lane >> 2, tig = lane & 3;
    int warpId = tid >> 5, wM = warpId & 3, wN = warpId >> 2;
    int r0 = wM*16, n0 = wN*32;

    // Q fragments (k = feature), reused by stage 1 and stage 3
    unsigned aQ[8][4];
    #pragma unroll
    for (int ks = 0; ks < 8; ks++) {
        int k0 = ks*8;
        aQ[ks][0] = __float_as_uint(QS[r0 + gid    ][k0 + tig]);
        aQ[ks][1] = __float_as_uint(QS[r0 + gid + 8][k0 + tig]);
        aQ[ks][2] = __float_as_uint(QS[r0 + gid    ][k0 + tig + 4]);
        aQ[ks][3] = __float_as_uint(QS[r0 + gid + 8][k0 + tig + 4]);
    }

    // stage 1: P = Q K^T
    float p[4][4];
    #pragma unroll
    for (int ni = 0; ni < 4; ni++)
        #pragma unroll
        for (int j = 0; j < 4; j++) p[ni][j] = 0.f;
    #pragma unroll
    for (int ks = 0; ks < 8; ks++) {
        int k0 = ks*8;
        #pragma unroll
        for (int ni = 0; ni < 4; ni++) {
            int cb = n0 + ni*8 + gid;
            unsigned b0 = __float_as_uint(KP[cb][k0 + tig]);
            unsigned b1 = __float_as_uint(KP[cb][k0 + tig + 4]);
            mma_tf32(p[ni], aQ[ks][0], aQ[ks][1], aQ[ks][2], aQ[ks][3], b0, b1);
        }
    }
    __syncthreads();

    // write masked tf32 P over K
    #pragma unroll
    for (int ni = 0; ni < 4; ni++) {
        int col = n0 + ni*8 + tig*2;
        int row1 = r0 + gid, row2 = r0 + gid + 8;
        KP[row1][col]     = (col     <= row1) ? f2tf32f(p[ni][0]) : 0.f;
        KP[row1][col + 1] = (col + 1 <= row1) ? f2tf32f(p[ni][1]) : 0.f;
        KP[row2][col]     = (col     <= row2) ? f2tf32f(p[ni][2]) : 0.f;
        KP[row2][col + 1] = (col + 1 <= row2) ? f2tf32f(p[ni][3]) : 0.f;
    }
    CP_WAIT0();      // S prefetch done
    __syncthreads();

    // stages 2+3: O = P V + Q S
    float o[4][4];
    #pragma unroll
    for (int ni = 0; ni < 4; ni++)
        #pragma unroll
        for (int j = 0; j < 4; j++) o[ni][j] = 0.f;
    #pragma unroll
    for (int ks = 0; ks < 8; ks++) {
        int k0 = ks*8;
        unsigned a0 = __float_as_uint(KP[r0 + gid    ][k0 + tig]);
        unsigned a1 = __float_as_uint(KP[r0 + gid + 8][k0 + tig]);
        unsigned a2 = __float_as_uint(KP[r0 + gid    ][k0 + tig + 4]);
        unsigned a3 = __float_as_uint(KP[r0 + gid + 8][k0 + tig + 4]);
        #pragma unroll
        for (int ni = 0; ni < 4; ni++) {
            int cb = n0 + ni*8 + gid;
            unsigned b0 = __float_as_uint(Vs[k0 + tig    ][cb]);
            unsigned b1 = __float_as_uint(Vs[k0 + tig + 4][cb]);
            mma_tf32(o[ni], a0, a1, a2, a3, b0, b1);
            unsigned s0 = __float_as_uint(Ss[k0 + tig    ][cb]);
            unsigned s1 = __float_as_uint(Ss[k0 + tig + 4][cb]);
            mma_tf32(o[ni], aQ[ks][0], aQ[ks][1], aQ[ks][2], aQ[ks][3], s0, s1);
        }
    }

    // epilogue: out[t,b,col..col+1] += alpha * o
    #pragma unroll
    for (int rr = 0; rr < 2; rr++) {
        int r = r0 + gid + rr*8;
        if (r >= L) continue;
        int idx = (ci << 6) + r;
        int t; float alpha;
        if (m == 0) { t = idx; alpha = 1.f; }
        else        { t = g_tok[segbase + idx]; alpha = g_pa[segbase + idx]; }
        float* op = out + ((size_t)t*B_ + b)*HD;
        #pragma unroll
        for (int ni = 0; ni < 4; ni++) {
            int col = n0 + ni*8 + tig*2;
            atomicAdd(op + col,     alpha * o[ni][rr*2]);
            atomicAdd(op + col + 1, alpha * o[ni][rr*2 + 1]);
        }
    }
}

// ---------------- launch ----------------
extern "C" void kernel_launch(void* const* d_in, const int* in_sizes, int n_in,
                              void* d_out, int out_size)
{
    const float* X  = (const float*)d_in[0];
    const float* M0 = (const float*)d_in[1];
    const float* Wq = (const float*)d_in[2];
    const float* bq = (const float*)d_in[3];
    const float* Wk = (const float*)d_in[4];
    const float* bk = (const float*)d_in[5];
    const float* Wv = (const float*)d_in[6];
    const float* bv = (const float*)d_in[7];
    const float* Wg = (const float*)d_in[8];
    const float* bg = (const float*)d_in[9];
    float* out = (float*)d_out;

    cudaFuncSetAttribute(proj_kernel,
                         cudaFuncAttributeMaxDynamicSharedMemorySize, KV_SMEM);
    cudaFuncSetAttribute(chunk_o_kernel,
                         cudaFuncAttributeMaxDynamicSharedMemorySize, O_SMEM);

    prep_kernel<<<GATE_BLKS + ZERO_BLKS + WCONV_BLKS, 256>>>(X, Wg, bg, Wq, Wk, Wv, out);
    pack_kernel<<<64, 1024>>>();
    proj_kernel<<<KV_BLKS + 256, 256, KV_SMEM>>>(bq, bk, bv);
    prefix_kernel<<<dim3(B_*MP1, 16), 256>>>(M0);
    chunk_o_kernel<<<dim3(32, MP1, B_), 256, O_SMEM>>>(out);
}